// round 1
// baseline (speedup 1.0000x reference)
#include <cuda_runtime.h>
#include <cuda_bf16.h>
#include <math.h>

// ---------------- static config ----------------
#define TB 2
#define SS 2048
#define DD 1024
#define HH 16
#define HDD 64
#define ROT 32
#define LQ 512
#define LKV 256
#define FF 1024
#define NR 7
#define CAP 585
#define TT (TB*SS)   // 4096 tokens

// ---------------- device scratch ----------------
__device__ float g_xn [TT*DD];
__device__ float g_zq [TT*LQ];
__device__ float g_zkv[TT*LKV];
__device__ float g_qrf[TT*DD];
__device__ float g_krf[TT*DD];
__device__ float g_q  [TT*DD];
__device__ float g_k  [TT*DD];
__device__ float g_v  [TT*DD];
__device__ float g_ao [TT*DD];
__device__ float g_x1 [TT*DD];
__device__ float g_xn2[TT*DD];
__device__ float g_h1 [TT*2*FF];
__device__ float g_hs [TT*FF];
__device__ float g_aff[TT*NR];
__device__ int2  g_top[TT];
__device__ int   g_selidx[NR*CAP];
__device__ float g_selw  [NR*CAP];
__device__ float g_gath[NR*CAP*DD];
__device__ float g_hr  [NR*CAP*2*FF];
__device__ float g_hr2 [NR*CAP*FF];
__device__ float g_eout[NR*CAP*DD];

// ---------------- RMSNorm ----------------
__global__ void rmsnorm_kernel(const float* __restrict__ x,
                               const float* __restrict__ w,
                               float* __restrict__ o) {
    int t = blockIdx.x;
    int tid = threadIdx.x;                 // 256 threads, 4 floats each
    __shared__ float red[256];
    const float4* xr = (const float4*)(x + (long long)t * DD);
    float4 v = xr[tid];
    float ss = v.x*v.x + v.y*v.y + v.z*v.z + v.w*v.w;
    red[tid] = ss; __syncthreads();
    for (int off = 128; off > 0; off >>= 1) {
        if (tid < off) red[tid] += red[tid + off];
        __syncthreads();
    }
    float inv = rsqrtf(red[0] / (float)DD + 1e-6f);
    const float4* wr = (const float4*)w;
    float4 wv = wr[tid];
    float4 ov = make_float4(v.x*inv*wv.x, v.y*inv*wv.y, v.z*inv*wv.z, v.w*inv*wv.w);
    ((float4*)(o + (long long)t * DD))[tid] = ov;
}

// ---------------- SGEMM: C = A[MxK] @ B[KxN] (+Add), row-major, batched ----------------
// BM=BN=64, BK=16, 256 threads, 4x4 micro-tile. Requires K%16==0, N%64==0.
__global__ void sgemm_kernel(const float* __restrict__ A,
                             const float* __restrict__ B,
                             float* __restrict__ C,
                             const float* __restrict__ Add,
                             int M, int N, int K,
                             long long sA, long long sB, long long sC) {
    int z = blockIdx.z;
    A += (long long)z * sA;
    B += (long long)z * sB;
    C += (long long)z * sC;
    if (Add) Add += (long long)z * sC;

    int m0 = blockIdx.y * 64, n0 = blockIdx.x * 64;
    int tid = threadIdx.x;
    int tx = tid & 15, ty = tid >> 4;

    __shared__ __align__(16) float As[16][64];
    __shared__ __align__(16) float Bs[16][64];

    float acc[4][4];
#pragma unroll
    for (int i = 0; i < 4; i++)
#pragma unroll
        for (int j = 0; j < 4; j++) acc[i][j] = 0.f;

    int arow = tid >> 2;          // 0..63
    int acol = (tid & 3) * 4;     // 0,4,8,12
    int brow = tid >> 4;          // 0..15
    int bcol = (tid & 15) * 4;    // 0..60

    for (int k0 = 0; k0 < K; k0 += 16) {
        float4 av = make_float4(0.f, 0.f, 0.f, 0.f);
        if (m0 + arow < M)
            av = *(const float4*)&A[(long long)(m0 + arow) * K + k0 + acol];
        As[acol + 0][arow] = av.x;
        As[acol + 1][arow] = av.y;
        As[acol + 2][arow] = av.z;
        As[acol + 3][arow] = av.w;
        float4 bv = *(const float4*)&B[(long long)(k0 + brow) * N + n0 + bcol];
        *(float4*)&Bs[brow][bcol] = bv;
        __syncthreads();
#pragma unroll
        for (int kk = 0; kk < 16; kk++) {
            float4 a = *(const float4*)&As[kk][ty * 4];
            float4 b = *(const float4*)&Bs[kk][tx * 4];
            acc[0][0] += a.x*b.x; acc[0][1] += a.x*b.y; acc[0][2] += a.x*b.z; acc[0][3] += a.x*b.w;
            acc[1][0] += a.y*b.x; acc[1][1] += a.y*b.y; acc[1][2] += a.y*b.z; acc[1][3] += a.y*b.w;
            acc[2][0] += a.z*b.x; acc[2][1] += a.z*b.y; acc[2][2] += a.z*b.z; acc[2][3] += a.z*b.w;
            acc[3][0] += a.w*b.x; acc[3][1] += a.w*b.y; acc[3][2] += a.w*b.z; acc[3][3] += a.w*b.w;
        }
        __syncthreads();
    }

#pragma unroll
    for (int i = 0; i < 4; i++) {
        int row = m0 + ty * 4 + i;
        if (row < M) {
            long long off = (long long)row * N + n0 + tx * 4;
            float4 r = make_float4(acc[i][0], acc[i][1], acc[i][2], acc[i][3]);
            if (Add) {
                float4 ad = *(const float4*)&Add[off];
                r.x += ad.x; r.y += ad.y; r.z += ad.z; r.w += ad.w;
            }
            *(float4*)&C[off] = r;
        }
    }
}

// ---------------- RoPE: fill rotary half of q/k ----------------
__global__ void rope_kernel() {
    int idx = blockIdx.x * blockDim.x + threadIdx.x;    // TT*HH*ROT = 2M
    if (idx >= TT * HH * ROT) return;
    int j = idx & (ROT - 1);
    int h = (idx >> 5) & (HH - 1);
    int t = idx >> 9;
    int s = t & (SS - 1);
    int i = j & 15;
    float invf = __expf(-9.210340371976184f * (float)i / 16.f);  // ln(10000)
    float ang = (float)s * invf;
    float sn, c;
    sincosf(ang, &sn, &c);
    long long base = (long long)t * DD + h * HDD;
    float qr = g_qrf[base + j];
    float kr = g_krf[base + j];
    float qo = (j < 16) ? -g_qrf[base + j + 16] : g_qrf[base + j - 16];
    float ko = (j < 16) ? -g_krf[base + j + 16] : g_krf[base + j - 16];
    g_q[base + 32 + j] = qr * c + qo * sn;
    g_k[base + 32 + j] = kr * c + ko * sn;
}

// ---------------- causal attention, online softmax ----------------
__global__ void attn_kernel() {
    int qi = blockIdx.x;
    int bh = blockIdx.y;
    int b = bh >> 4, h = bh & 15;
    int tq = b * SS + qi;
    int tid = threadIdx.x;     // 128 threads

    __shared__ __align__(16) float qs[64];
    __shared__ float ps[128];
    __shared__ float red[128];

    if (tid < 64) qs[tid] = g_q[(long long)tq * DD + h * HDD + tid];
    __syncthreads();

    float m = -1e30f, l = 0.f, acc = 0.f;
    int d = tid & 63, half = tid >> 6;
    const float* Kb = g_k + (long long)b * SS * DD + h * HDD;
    const float* Vb = g_v + (long long)b * SS * DD + h * HDD;

    for (int k0 = 0; k0 <= qi; k0 += 128) {
        int key = k0 + tid;
        float s = -1e30f;
        if (key <= qi) {
            const float4* kp = (const float4*)(Kb + (long long)key * DD);
            const float4* qp = (const float4*)qs;
            float dot = 0.f;
#pragma unroll
            for (int i = 0; i < 16; i++) {
                float4 kv = kp[i], qv = qp[i];
                dot += kv.x*qv.x + kv.y*qv.y + kv.z*qv.z + kv.w*qv.w;
            }
            s = dot * 0.125f;
        }
        red[tid] = s; __syncthreads();
        for (int off = 64; off > 0; off >>= 1) {
            if (tid < off) red[tid] = fmaxf(red[tid], red[tid + off]);
            __syncthreads();
        }
        float nm = fmaxf(m, red[0]);
        __syncthreads();
        float p = __expf(s - nm);           // underflows to 0 for masked keys
        ps[tid] = p; red[tid] = p; __syncthreads();
        for (int off = 64; off > 0; off >>= 1) {
            if (tid < off) red[tid] += red[tid + off];
            __syncthreads();
        }
        float csum = red[0];
        float corr = __expf(m - nm);
        l = l * corr + csum;
        m = nm;
        acc *= corr;
        int nk = min(128, qi - k0 + 1);
        for (int j = half; j < nk; j += 2)
            acc += ps[j] * Vb[(long long)(k0 + j) * DD + d];
        __syncthreads();
    }
    red[tid] = acc; __syncthreads();
    if (tid < 64) {
        float o = (red[tid] + red[tid + 64]) / l;
        g_ao[(long long)tq * DD + h * HDD + tid] = o;
    }
}

// ---------------- SwiGLU ----------------
__global__ void swiglu_kernel(const float* __restrict__ in,
                              float* __restrict__ out, int rows) {
    long long i = (long long)blockIdx.x * blockDim.x + threadIdx.x;
    if (i >= (long long)rows * FF) return;
    long long r = i / FF;
    int f = (int)(i - r * FF);
    float a = in[r * 2 * FF + f];
    float bv = in[r * 2 * FF + FF + f];
    out[i] = a * (bv / (1.f + __expf(-bv)));
}

// ---------------- gating: aff = sigmoid(xn2 @ Wgate + bias) ----------------
__global__ void gate_kernel(const float* __restrict__ Wg,
                            const float* __restrict__ bias) {
    int t = blockIdx.x;
    int w = threadIdx.x >> 5, lane = threadIdx.x & 31;
    if (w >= NR) return;
    float s = 0.f;
    const float* xr = g_xn2 + (long long)t * DD;
    for (int i = lane; i < DD; i += 32) s += xr[i] * Wg[i * NR + w];
#pragma unroll
    for (int off = 16; off > 0; off >>= 1)
        s += __shfl_down_sync(0xffffffff, s, off);
    if (lane == 0)
        g_aff[t * NR + w] = 1.f / (1.f + __expf(-(s + bias[w])));
}

// ---------------- per-token top-2 ----------------
__global__ void top2_kernel() {
    int t = blockIdx.x * blockDim.x + threadIdx.x;
    if (t >= TT) return;
    float a[NR];
#pragma unroll
    for (int e = 0; e < NR; e++) a[e] = g_aff[t * NR + e];
    int e1 = 0; float b1 = a[0];
#pragma unroll
    for (int e = 1; e < NR; e++) if (a[e] > b1) { b1 = a[e]; e1 = e; }
    int e2 = -1; float b2 = -1.f;
#pragma unroll
    for (int e = 0; e < NR; e++) if (e != e1 && a[e] > b2) { b2 = a[e]; e2 = e; }
    g_top[t] = make_int2(e1, e2);
}

// ---------------- per-expert capacity selection (bitonic sort 4096) ----------------
__global__ void select_kernel() {
    __shared__ unsigned long long keys[TT];
    int e = blockIdx.x;
    int tid = threadIdx.x;   // 1024
    for (int i = tid; i < TT; i += 1024) {
        int2 tp = g_top[i];
        unsigned hi;
        if (tp.x == e || tp.y == e) {
            unsigned ev = __float_as_uint(g_aff[i * NR + e]);  // positive
            hi = ~ev;                                           // larger aff -> smaller key
        } else {
            hi = 0xFFFFFFFFu;
        }
        keys[i] = ((unsigned long long)hi << 32) | (unsigned)i;
    }
    __syncthreads();
    // bitonic sort ascending
    for (int ksz = 2; ksz <= TT; ksz <<= 1) {
        for (int j = ksz >> 1; j > 0; j >>= 1) {
            for (int base = tid; base < TT / 2; base += 1024) {
                int i = ((base & ~(j - 1)) << 1) | (base & (j - 1));
                int p = i + j;
                bool up = ((i & ksz) == 0);
                unsigned long long a = keys[i], b2 = keys[p];
                if ((a > b2) == up) { keys[i] = b2; keys[p] = a; }
            }
            __syncthreads();
        }
    }
    for (int c = tid; c < CAP; c += 1024) {
        unsigned long long kk = keys[c];
        int idx = (int)(kk & 0xFFFFFFFFu);
        bool valid = (unsigned)(kk >> 32) != 0xFFFFFFFFu;
        g_selidx[e * CAP + c] = idx;
        g_selw[e * CAP + c] = valid ? g_aff[idx * NR + e] : 0.f;
    }
}

// ---------------- gather selected tokens ----------------
__global__ void gather_kernel() {
    int row = blockIdx.x;          // NR*CAP
    int t = g_selidx[row];
    int i = threadIdx.x * 4;       // 256 threads * 4 = 1024
    float4 v = *(const float4*)&g_xn2[(long long)t * DD + i];
    *(float4*)&g_gath[(long long)row * DD + i] = v;
}

// ---------------- scatter-add routed outputs ----------------
__global__ void scatter_kernel(float* __restrict__ out) {
    int row = blockIdx.x;
    float w = g_selw[row];
    if (w == 0.f) return;
    int t = g_selidx[row];
    int i = threadIdx.x * 4;
    const float* src = &g_eout[(long long)row * DD + i];
    float* dst = &out[(long long)t * DD + i];
#pragma unroll
    for (int j = 0; j < 4; j++) atomicAdd(dst + j, src[j] * w);
}

// ---------------- host helpers ----------------
static float* sym(const void* s) {
    void* p = nullptr;
    cudaGetSymbolAddress(&p, (const void*)s);
    return (float*)p;
}

static void run_gemm(const float* A, const float* B, float* C, const float* Add,
                     int M, int N, int K, int batch,
                     long long sA, long long sB, long long sC) {
    dim3 grid((N + 63) / 64, (M + 63) / 64, batch);
    sgemm_kernel<<<grid, 256>>>(A, B, C, Add, M, N, K, sA, sB, sC);
}

extern "C" void kernel_launch(void* const* d_in, const int* in_sizes, int n_in,
                              void* d_out, int out_size) {
    const float* x       = (const float*)d_in[0];
    const float* Wq_lat  = (const float*)d_in[2];
    const float* Wkv_lat = (const float*)d_in[3];
    const float* Wrot_q  = (const float*)d_in[4];
    const float* Wrot_k  = (const float*)d_in[5];
    const float* Wq_up   = (const float*)d_in[6];
    const float* Wk_up   = (const float*)d_in[7];
    const float* Wv_up   = (const float*)d_in[8];
    const float* Wout    = (const float*)d_in[9];
    const float* n1w     = (const float*)d_in[10];
    const float* n2w     = (const float*)d_in[11];
    const float* Ws1     = (const float*)d_in[12];
    const float* Ws2     = (const float*)d_in[13];
    const float* Wr1     = (const float*)d_in[14];
    const float* Wr2     = (const float*)d_in[15];
    const float* Wgate   = (const float*)d_in[16];
    const float* ebias   = (const float*)d_in[17];
    float* out = (float*)d_out;

    float* p_xn  = sym(&g_xn);
    float* p_zq  = sym(&g_zq);
    float* p_zkv = sym(&g_zkv);
    float* p_qrf = sym(&g_qrf);
    float* p_krf = sym(&g_krf);
    float* p_q   = sym(&g_q);
    float* p_k   = sym(&g_k);
    float* p_v   = sym(&g_v);
    float* p_ao  = sym(&g_ao);
    float* p_x1  = sym(&g_x1);
    float* p_xn2 = sym(&g_xn2);
    float* p_h1  = sym(&g_h1);
    float* p_hs  = sym(&g_hs);
    float* p_ga  = sym(&g_gath);
    float* p_hr  = sym(&g_hr);
    float* p_hr2 = sym(&g_hr2);
    float* p_eo  = sym(&g_eout);

    // ---- sublayer 1 ----
    rmsnorm_kernel<<<TT, 256>>>(x, n1w, p_xn);
    run_gemm(p_xn,  Wq_lat,  p_zq,  nullptr, TT, LQ,  DD, 1, 0, 0, 0);
    run_gemm(p_xn,  Wkv_lat, p_zkv, nullptr, TT, LKV, DD, 1, 0, 0, 0);
    run_gemm(p_zq,  Wrot_q,  p_qrf, nullptr, TT, DD, LQ,  1, 0, 0, 0);
    run_gemm(p_zkv, Wrot_k,  p_krf, nullptr, TT, DD, LKV, 1, 0, 0, 0);
    run_gemm(p_zq,  Wq_up,   p_q,   nullptr, TT, DD, LQ,  1, 0, 0, 0);
    run_gemm(p_zkv, Wk_up,   p_k,   nullptr, TT, DD, LKV, 1, 0, 0, 0);
    run_gemm(p_zkv, Wv_up,   p_v,   nullptr, TT, DD, LKV, 1, 0, 0, 0);
    rope_kernel<<<(TT * HH * ROT + 255) / 256, 256>>>();
    attn_kernel<<<dim3(SS, TB * HH), 128>>>();
    run_gemm(p_ao, Wout, p_x1, x, TT, DD, DD, 1, 0, 0, 0);

    // ---- sublayer 2 ----
    rmsnorm_kernel<<<TT, 256>>>(p_x1, n2w, p_xn2);
    // shared expert
    run_gemm(p_xn2, Ws1, p_h1, nullptr, TT, 2 * FF, DD, 1, 0, 0, 0);
    swiglu_kernel<<<(TT * FF + 255) / 256, 256>>>(p_h1, p_hs, TT);
    run_gemm(p_hs, Ws2, out, p_x1, TT, DD, FF, 1, 0, 0, 0);  // out = x1 + shared
    // routing
    gate_kernel<<<TT, 256>>>(Wgate, ebias);
    top2_kernel<<<(TT + 255) / 256, 256>>>();
    select_kernel<<<NR, 1024>>>();
    gather_kernel<<<NR * CAP, 256>>>();
    // routed experts (batched)
    run_gemm(p_ga, Wr1, p_hr, nullptr, CAP, 2 * FF, DD, NR,
             (long long)CAP * DD, (long long)DD * 2 * FF, (long long)CAP * 2 * FF);
    swiglu_kernel<<<(NR * CAP * FF + 255) / 256, 256>>>(p_hr, p_hr2, NR * CAP);
    run_gemm(p_hr2, Wr2, p_eo, nullptr, CAP, DD, FF, NR,
             (long long)CAP * FF, (long long)FF * DD, (long long)CAP * FF);
    scatter_kernel<<<NR * CAP, 256>>>(out);
}

// round 2
// speedup vs baseline: 2.6111x; 2.6111x over previous
#include <cuda_runtime.h>
#include <cuda_bf16.h>
#include <math.h>

// ---------------- static config ----------------
#define TB 2
#define SS 2048
#define DD 1024
#define HH 16
#define HDD 64
#define ROT 32
#define LQ 512
#define LKV 256
#define FF 1024
#define NR 7
#define CAP 585
#define TT (TB*SS)   // 4096 tokens

// ---------------- device scratch ----------------
__device__ float g_xn [TT*DD];
__device__ float g_zq [TT*LQ];
__device__ float g_zkv[TT*LKV];
__device__ float g_qrf[TT*DD];
__device__ float g_krf[TT*DD];
__device__ float g_q  [TT*DD];
__device__ float g_k  [TT*DD];
__device__ float g_v  [TT*DD];
__device__ float g_ao [TT*DD];
__device__ float g_x1 [TT*DD];
__device__ float g_xn2[TT*DD];
__device__ float g_h1 [TT*2*FF];
__device__ float g_hs [TT*FF];
__device__ float g_aff[TT*NR];
__device__ int2  g_top[TT];
__device__ int   g_selidx[NR*CAP];
__device__ float g_selw  [NR*CAP];
__device__ float g_gath[NR*CAP*DD];
__device__ float g_hr  [NR*CAP*2*FF];
__device__ float g_hr2 [NR*CAP*FF];
__device__ float g_eout[NR*CAP*DD];

// ---------------- RMSNorm ----------------
__global__ void rmsnorm_kernel(const float* __restrict__ x,
                               const float* __restrict__ w,
                               float* __restrict__ o) {
    int t = blockIdx.x;
    int tid = threadIdx.x;                 // 256 threads, 4 floats each
    __shared__ float red[256];
    const float4* xr = (const float4*)(x + (long long)t * DD);
    float4 v = xr[tid];
    float ss = v.x*v.x + v.y*v.y + v.z*v.z + v.w*v.w;
    red[tid] = ss; __syncthreads();
    for (int off = 128; off > 0; off >>= 1) {
        if (tid < off) red[tid] += red[tid + off];
        __syncthreads();
    }
    float inv = rsqrtf(red[0] / (float)DD + 1e-6f);
    const float4* wr = (const float4*)w;
    float4 wv = wr[tid];
    float4 ov = make_float4(v.x*inv*wv.x, v.y*inv*wv.y, v.z*inv*wv.z, v.w*inv*wv.w);
    ((float4*)(o + (long long)t * DD))[tid] = ov;
}

// ---------------- SGEMM 64x64x16 (narrow N) ----------------
__global__ void sgemm_kernel(const float* __restrict__ A,
                             const float* __restrict__ B,
                             float* __restrict__ C,
                             const float* __restrict__ Add,
                             int M, int N, int K,
                             long long sA, long long sB, long long sC) {
    int z = blockIdx.z;
    A += (long long)z * sA;
    B += (long long)z * sB;
    C += (long long)z * sC;
    if (Add) Add += (long long)z * sC;

    int m0 = blockIdx.y * 64, n0 = blockIdx.x * 64;
    int tid = threadIdx.x;
    int tx = tid & 15, ty = tid >> 4;

    __shared__ __align__(16) float As[16][64];
    __shared__ __align__(16) float Bs[16][64];

    float acc[4][4];
#pragma unroll
    for (int i = 0; i < 4; i++)
#pragma unroll
        for (int j = 0; j < 4; j++) acc[i][j] = 0.f;

    int arow = tid >> 2;
    int acol = (tid & 3) * 4;
    int brow = tid >> 4;
    int bcol = (tid & 15) * 4;

    for (int k0 = 0; k0 < K; k0 += 16) {
        float4 av = make_float4(0.f, 0.f, 0.f, 0.f);
        if (m0 + arow < M)
            av = *(const float4*)&A[(long long)(m0 + arow) * K + k0 + acol];
        As[acol + 0][arow] = av.x;
        As[acol + 1][arow] = av.y;
        As[acol + 2][arow] = av.z;
        As[acol + 3][arow] = av.w;
        float4 bv = *(const float4*)&B[(long long)(k0 + brow) * N + n0 + bcol];
        *(float4*)&Bs[brow][bcol] = bv;
        __syncthreads();
#pragma unroll
        for (int kk = 0; kk < 16; kk++) {
            float4 a = *(const float4*)&As[kk][ty * 4];
            float4 b = *(const float4*)&Bs[kk][tx * 4];
            acc[0][0] += a.x*b.x; acc[0][1] += a.x*b.y; acc[0][2] += a.x*b.z; acc[0][3] += a.x*b.w;
            acc[1][0] += a.y*b.x; acc[1][1] += a.y*b.y; acc[1][2] += a.y*b.z; acc[1][3] += a.y*b.w;
            acc[2][0] += a.z*b.x; acc[2][1] += a.z*b.y; acc[2][2] += a.z*b.z; acc[2][3] += a.z*b.w;
            acc[3][0] += a.w*b.x; acc[3][1] += a.w*b.y; acc[3][2] += a.w*b.z; acc[3][3] += a.w*b.w;
        }
        __syncthreads();
    }

#pragma unroll
    for (int i = 0; i < 4; i++) {
        int row = m0 + ty * 4 + i;
        if (row < M) {
            long long off = (long long)row * N + n0 + tx * 4;
            float4 r = make_float4(acc[i][0], acc[i][1], acc[i][2], acc[i][3]);
            if (Add) {
                float4 ad = *(const float4*)&Add[off];
                r.x += ad.x; r.y += ad.y; r.z += ad.z; r.w += ad.w;
            }
            *(float4*)&C[off] = r;
        }
    }
}

// ---------------- SGEMM 128x128x16, 8x8 micro-tile (split fragments) ----------------
__global__ void __launch_bounds__(256)
sgemm128_kernel(const float* __restrict__ A,
                const float* __restrict__ B,
                float* __restrict__ C,
                const float* __restrict__ Add,
                int M, int N, int K,
                long long sA, long long sB, long long sC) {
    int z = blockIdx.z;
    A += (long long)z * sA;
    B += (long long)z * sB;
    C += (long long)z * sC;
    if (Add) Add += (long long)z * sC;

    int m0 = blockIdx.y * 128, n0 = blockIdx.x * 128;
    int tid = threadIdx.x;
    int ty = tid >> 4, tx = tid & 15;

    __shared__ __align__(16) float As[16][128];
    __shared__ __align__(16) float Bs[16][128];

    float acc[8][8];
#pragma unroll
    for (int i = 0; i < 8; i++)
#pragma unroll
        for (int j = 0; j < 8; j++) acc[i][j] = 0.f;

    int arow = tid >> 1;          // 0..127
    int acol = (tid & 1) * 8;     // 0 or 8
    int brow = tid >> 4;          // 0..15
    int bcol = (tid & 15) * 8;    // 0..120

    for (int k0 = 0; k0 < K; k0 += 16) {
        float4 av0 = make_float4(0.f,0.f,0.f,0.f), av1 = av0;
        if (m0 + arow < M) {
            av0 = *(const float4*)&A[(long long)(m0 + arow) * K + k0 + acol];
            av1 = *(const float4*)&A[(long long)(m0 + arow) * K + k0 + acol + 4];
        }
        As[acol + 0][arow] = av0.x;
        As[acol + 1][arow] = av0.y;
        As[acol + 2][arow] = av0.z;
        As[acol + 3][arow] = av0.w;
        As[acol + 4][arow] = av1.x;
        As[acol + 5][arow] = av1.y;
        As[acol + 6][arow] = av1.z;
        As[acol + 7][arow] = av1.w;
        float4 bv0 = *(const float4*)&B[(long long)(k0 + brow) * N + n0 + bcol];
        float4 bv1 = *(const float4*)&B[(long long)(k0 + brow) * N + n0 + bcol + 4];
        *(float4*)&Bs[brow][bcol] = bv0;
        *(float4*)&Bs[brow][bcol + 4] = bv1;
        __syncthreads();
#pragma unroll
        for (int kk = 0; kk < 16; kk++) {
            float a[8], b[8];
            *(float4*)&a[0] = *(const float4*)&As[kk][ty * 4];
            *(float4*)&a[4] = *(const float4*)&As[kk][64 + ty * 4];
            *(float4*)&b[0] = *(const float4*)&Bs[kk][tx * 4];
            *(float4*)&b[4] = *(const float4*)&Bs[kk][64 + tx * 4];
#pragma unroll
            for (int i = 0; i < 8; i++)
#pragma unroll
                for (int j = 0; j < 8; j++)
                    acc[i][j] += a[i] * b[j];
        }
        __syncthreads();
    }

#pragma unroll
    for (int hi = 0; hi < 2; hi++) {
#pragma unroll
        for (int ii = 0; ii < 4; ii++) {
            int row = m0 + hi * 64 + ty * 4 + ii;
            if (row >= M) continue;
#pragma unroll
            for (int hj = 0; hj < 2; hj++) {
                long long off = (long long)row * N + n0 + hj * 64 + tx * 4;
                int ai = hi * 4 + ii;
                float4 r = make_float4(acc[ai][hj*4+0], acc[ai][hj*4+1],
                                       acc[ai][hj*4+2], acc[ai][hj*4+3]);
                if (Add) {
                    float4 ad = *(const float4*)&Add[off];
                    r.x += ad.x; r.y += ad.y; r.z += ad.z; r.w += ad.w;
                }
                *(float4*)&C[off] = r;
            }
        }
    }
}

// ---------------- RoPE: fill rotary half of q/k ----------------
__global__ void rope_kernel() {
    int idx = blockIdx.x * blockDim.x + threadIdx.x;    // TT*HH*ROT = 2M
    if (idx >= TT * HH * ROT) return;
    int j = idx & (ROT - 1);
    int h = (idx >> 5) & (HH - 1);
    int t = idx >> 9;
    int s = t & (SS - 1);
    int i = j & 15;
    float invf = __expf(-9.210340371976184f * (float)i / 16.f);  // ln(10000)
    float ang = (float)s * invf;
    float sn, c;
    sincosf(ang, &sn, &c);
    long long base = (long long)t * DD + h * HDD;
    float qr = g_qrf[base + j];
    float kr = g_krf[base + j];
    float qo = (j < 16) ? -g_qrf[base + j + 16] : g_qrf[base + j - 16];
    float ko = (j < 16) ? -g_krf[base + j + 16] : g_krf[base + j - 16];
    g_q[base + 32 + j] = qr * c + qo * sn;
    g_k[base + 32 + j] = kr * c + ko * sn;
}

// ---------------- flash attention: 64 queries x 64 keys per tile ----------------
__global__ void __launch_bounds__(256) fattn_kernel() {
    const int q0 = blockIdx.x * 64;
    const int bh = blockIdx.y;
    const int b = bh >> 4, h = bh & 15;
    const int tid = threadIdx.x;
    const int ty = tid >> 4, tx = tid & 15;

    __shared__ __align__(16) float Qs[64][64];   // [d][row]
    __shared__ __align__(16) float KPs[64][64];  // K phase: [d][col]; P phase: [row][col]
    __shared__ __align__(16) float Vs[64][64];   // [col][d]

    const float* Qg = g_q + ((long long)(b * SS + q0)) * DD + h * HDD;
    const float* Kg = g_k + ((long long)b * SS) * DD + h * HDD;
    const float* Vg = g_v + ((long long)b * SS) * DD + h * HDD;

    {
        int r = tid >> 2;
        int c0 = (tid & 3) * 16;
#pragma unroll
        for (int u = 0; u < 4; u++) {
            float4 v = *(const float4*)&Qg[(long long)r * DD + c0 + u * 4];
            Qs[c0 + u*4 + 0][r] = v.x;
            Qs[c0 + u*4 + 1][r] = v.y;
            Qs[c0 + u*4 + 2][r] = v.z;
            Qs[c0 + u*4 + 3][r] = v.w;
        }
    }

    float O[4][4];
#pragma unroll
    for (int i = 0; i < 4; i++)
#pragma unroll
        for (int j = 0; j < 4; j++) O[i][j] = 0.f;
    float m[4] = {-1e30f, -1e30f, -1e30f, -1e30f};
    float l[4] = {0.f, 0.f, 0.f, 0.f};

    for (int k0 = 0; k0 <= q0; k0 += 64) {
        {
            int r = tid >> 2;
            int c0 = (tid & 3) * 16;
#pragma unroll
            for (int u = 0; u < 4; u++) {
                float4 kv = *(const float4*)&Kg[(long long)(k0 + r) * DD + c0 + u * 4];
                KPs[c0 + u*4 + 0][r] = kv.x;
                KPs[c0 + u*4 + 1][r] = kv.y;
                KPs[c0 + u*4 + 2][r] = kv.z;
                KPs[c0 + u*4 + 3][r] = kv.w;
                *(float4*)&Vs[r][c0 + u*4] =
                    *(const float4*)&Vg[(long long)(k0 + r) * DD + c0 + u * 4];
            }
        }
        __syncthreads();

        // S = Q K^T (64x64), this thread: rows ty*4.., cols tx*4..
        float s[4][4];
#pragma unroll
        for (int i = 0; i < 4; i++)
#pragma unroll
            for (int j = 0; j < 4; j++) s[i][j] = 0.f;
#pragma unroll 8
        for (int d = 0; d < 64; d++) {
            float4 aa = *(const float4*)&Qs[d][ty * 4];
            float4 bb = *(const float4*)&KPs[d][tx * 4];
            s[0][0] += aa.x*bb.x; s[0][1] += aa.x*bb.y; s[0][2] += aa.x*bb.z; s[0][3] += aa.x*bb.w;
            s[1][0] += aa.y*bb.x; s[1][1] += aa.y*bb.y; s[1][2] += aa.y*bb.z; s[1][3] += aa.y*bb.w;
            s[2][0] += aa.z*bb.x; s[2][1] += aa.z*bb.y; s[2][2] += aa.z*bb.z; s[2][3] += aa.z*bb.w;
            s[3][0] += aa.w*bb.x; s[3][1] += aa.w*bb.y; s[3][2] += aa.w*bb.z; s[3][3] += aa.w*bb.w;
        }
        __syncthreads();   // K reads done; KPs can be reused for P

        if (k0 == q0) {
#pragma unroll
            for (int i = 0; i < 4; i++)
#pragma unroll
                for (int j = 0; j < 4; j++)
                    s[i][j] = (tx*4 + j <= ty*4 + i) ? s[i][j] * 0.125f : -1e30f;
        } else {
#pragma unroll
            for (int i = 0; i < 4; i++)
#pragma unroll
                for (int j = 0; j < 4; j++) s[i][j] *= 0.125f;
        }

#pragma unroll
        for (int i = 0; i < 4; i++) {
            float mx = fmaxf(fmaxf(s[i][0], s[i][1]), fmaxf(s[i][2], s[i][3]));
#pragma unroll
            for (int off = 1; off < 16; off <<= 1)
                mx = fmaxf(mx, __shfl_xor_sync(0xffffffffu, mx, off));
            float mn = fmaxf(m[i], mx);
            float corr = __expf(m[i] - mn);
            float p0 = __expf(s[i][0] - mn);
            float p1 = __expf(s[i][1] - mn);
            float p2 = __expf(s[i][2] - mn);
            float p3 = __expf(s[i][3] - mn);
            *(float4*)&KPs[ty*4 + i][tx*4] = make_float4(p0, p1, p2, p3);
            float sum = p0 + p1 + p2 + p3;
#pragma unroll
            for (int off = 1; off < 16; off <<= 1)
                sum += __shfl_xor_sync(0xffffffffu, sum, off);
            l[i] = l[i] * corr + sum;
            m[i] = mn;
            O[i][0] *= corr; O[i][1] *= corr; O[i][2] *= corr; O[i][3] *= corr;
        }
        __syncthreads();   // P visible to all

        // O += P V: rows ty*4.., dims tx*4..
#pragma unroll 8
        for (int c = 0; c < 64; c++) {
            float4 bb = *(const float4*)&Vs[c][tx * 4];
            float a0 = KPs[ty*4 + 0][c];
            float a1 = KPs[ty*4 + 1][c];
            float a2 = KPs[ty*4 + 2][c];
            float a3 = KPs[ty*4 + 3][c];
            O[0][0] += a0*bb.x; O[0][1] += a0*bb.y; O[0][2] += a0*bb.z; O[0][3] += a0*bb.w;
            O[1][0] += a1*bb.x; O[1][1] += a1*bb.y; O[1][2] += a1*bb.z; O[1][3] += a1*bb.w;
            O[2][0] += a2*bb.x; O[2][1] += a2*bb.y; O[2][2] += a2*bb.z; O[2][3] += a2*bb.w;
            O[3][0] += a3*bb.x; O[3][1] += a3*bb.y; O[3][2] += a3*bb.z; O[3][3] += a3*bb.w;
        }
        __syncthreads();   // before next tile overwrites smem
    }

    float* Og = g_ao + ((long long)(b * SS + q0)) * DD + h * HDD;
#pragma unroll
    for (int i = 0; i < 4; i++) {
        float inv = 1.f / l[i];
        float4 o = make_float4(O[i][0]*inv, O[i][1]*inv, O[i][2]*inv, O[i][3]*inv);
        *(float4*)&Og[(long long)(ty*4 + i) * DD + tx * 4] = o;
    }
}

// ---------------- SwiGLU ----------------
__global__ void swiglu_kernel(const float* __restrict__ in,
                              float* __restrict__ out, int rows) {
    long long i = (long long)blockIdx.x * blockDim.x + threadIdx.x;
    if (i >= (long long)rows * FF) return;
    long long r = i / FF;
    int f = (int)(i - r * FF);
    float a = in[r * 2 * FF + f];
    float bv = in[r * 2 * FF + FF + f];
    out[i] = a * (bv / (1.f + __expf(-bv)));
}

// ---------------- gating ----------------
__global__ void gate_kernel(const float* __restrict__ Wg,
                            const float* __restrict__ bias) {
    int t = blockIdx.x;
    int w = threadIdx.x >> 5, lane = threadIdx.x & 31;
    if (w >= NR) return;
    float s = 0.f;
    const float* xr = g_xn2 + (long long)t * DD;
    for (int i = lane; i < DD; i += 32) s += xr[i] * Wg[i * NR + w];
#pragma unroll
    for (int off = 16; off > 0; off >>= 1)
        s += __shfl_down_sync(0xffffffff, s, off);
    if (lane == 0)
        g_aff[t * NR + w] = 1.f / (1.f + __expf(-(s + bias[w])));
}

// ---------------- per-token top-2 ----------------
__global__ void top2_kernel() {
    int t = blockIdx.x * blockDim.x + threadIdx.x;
    if (t >= TT) return;
    float a[NR];
#pragma unroll
    for (int e = 0; e < NR; e++) a[e] = g_aff[t * NR + e];
    int e1 = 0; float b1 = a[0];
#pragma unroll
    for (int e = 1; e < NR; e++) if (a[e] > b1) { b1 = a[e]; e1 = e; }
    int e2 = -1; float b2 = -1.f;
#pragma unroll
    for (int e = 0; e < NR; e++) if (e != e1 && a[e] > b2) { b2 = a[e]; e2 = e; }
    g_top[t] = make_int2(e1, e2);
}

// ---------------- per-expert capacity selection ----------------
__global__ void select_kernel() {
    __shared__ unsigned long long keys[TT];
    int e = blockIdx.x;
    int tid = threadIdx.x;   // 1024
    for (int i = tid; i < TT; i += 1024) {
        int2 tp = g_top[i];
        unsigned hi;
        if (tp.x == e || tp.y == e) {
            unsigned ev = __float_as_uint(g_aff[i * NR + e]);
            hi = ~ev;
        } else {
            hi = 0xFFFFFFFFu;
        }
        keys[i] = ((unsigned long long)hi << 32) | (unsigned)i;
    }
    __syncthreads();
    for (int ksz = 2; ksz <= TT; ksz <<= 1) {
        for (int j = ksz >> 1; j > 0; j >>= 1) {
            for (int base = tid; base < TT / 2; base += 1024) {
                int i = ((base & ~(j - 1)) << 1) | (base & (j - 1));
                int p = i + j;
                bool up = ((i & ksz) == 0);
                unsigned long long a = keys[i], b2 = keys[p];
                if ((a > b2) == up) { keys[i] = b2; keys[p] = a; }
            }
            __syncthreads();
        }
    }
    for (int c = tid; c < CAP; c += 1024) {
        unsigned long long kk = keys[c];
        int idx = (int)(kk & 0xFFFFFFFFu);
        bool valid = (unsigned)(kk >> 32) != 0xFFFFFFFFu;
        g_selidx[e * CAP + c] = idx;
        g_selw[e * CAP + c] = valid ? g_aff[idx * NR + e] : 0.f;
    }
}

// ---------------- gather ----------------
__global__ void gather_kernel() {
    int row = blockIdx.x;
    int t = g_selidx[row];
    int i = threadIdx.x * 4;
    float4 v = *(const float4*)&g_xn2[(long long)t * DD + i];
    *(float4*)&g_gath[(long long)row * DD + i] = v;
}

// ---------------- scatter-add ----------------
__global__ void scatter_kernel(float* __restrict__ out) {
    int row = blockIdx.x;
    float w = g_selw[row];
    if (w == 0.f) return;
    int t = g_selidx[row];
    int i = threadIdx.x * 4;
    const float* src = &g_eout[(long long)row * DD + i];
    float* dst = &out[(long long)t * DD + i];
#pragma unroll
    for (int j = 0; j < 4; j++) atomicAdd(dst + j, src[j] * w);
}

// ---------------- host helpers ----------------
static float* sym(const void* s) {
    void* p = nullptr;
    cudaGetSymbolAddress(&p, (const void*)s);
    return (float*)p;
}

static void run_gemm64(const float* A, const float* B, float* C, const float* Add,
                       int M, int N, int K, int batch,
                       long long sA, long long sB, long long sC) {
    dim3 grid((N + 63) / 64, (M + 63) / 64, batch);
    sgemm_kernel<<<grid, 256>>>(A, B, C, Add, M, N, K, sA, sB, sC);
}

static void run_gemm128(const float* A, const float* B, float* C, const float* Add,
                        int M, int N, int K, int batch,
                        long long sA, long long sB, long long sC) {
    dim3 grid((N + 127) / 128, (M + 127) / 128, batch);
    sgemm128_kernel<<<grid, 256>>>(A, B, C, Add, M, N, K, sA, sB, sC);
}

extern "C" void kernel_launch(void* const* d_in, const int* in_sizes, int n_in,
                              void* d_out, int out_size) {
    const float* x       = (const float*)d_in[0];
    const float* Wq_lat  = (const float*)d_in[2];
    const float* Wkv_lat = (const float*)d_in[3];
    const float* Wrot_q  = (const float*)d_in[4];
    const float* Wrot_k  = (const float*)d_in[5];
    const float* Wq_up   = (const float*)d_in[6];
    const float* Wk_up   = (const float*)d_in[7];
    const float* Wv_up   = (const float*)d_in[8];
    const float* Wout    = (const float*)d_in[9];
    const float* n1w     = (const float*)d_in[10];
    const float* n2w     = (const float*)d_in[11];
    const float* Ws1     = (const float*)d_in[12];
    const float* Ws2     = (const float*)d_in[13];
    const float* Wr1     = (const float*)d_in[14];
    const float* Wr2     = (const float*)d_in[15];
    const float* Wgate   = (const float*)d_in[16];
    const float* ebias   = (const float*)d_in[17];
    float* out = (float*)d_out;

    float* p_xn  = sym(&g_xn);
    float* p_zq  = sym(&g_zq);
    float* p_zkv = sym(&g_zkv);
    float* p_qrf = sym(&g_qrf);
    float* p_krf = sym(&g_krf);
    float* p_q   = sym(&g_q);
    float* p_k   = sym(&g_k);
    float* p_v   = sym(&g_v);
    float* p_ao  = sym(&g_ao);
    float* p_x1  = sym(&g_x1);
    float* p_xn2 = sym(&g_xn2);
    float* p_h1  = sym(&g_h1);
    float* p_hs  = sym(&g_hs);
    float* p_ga  = sym(&g_gath);
    float* p_hr  = sym(&g_hr);
    float* p_hr2 = sym(&g_hr2);
    float* p_eo  = sym(&g_eout);

    // ---- sublayer 1 ----
    rmsnorm_kernel<<<TT, 256>>>(x, n1w, p_xn);
    run_gemm64 (p_xn,  Wq_lat,  p_zq,  nullptr, TT, LQ,  DD, 1, 0, 0, 0);
    run_gemm64 (p_xn,  Wkv_lat, p_zkv, nullptr, TT, LKV, DD, 1, 0, 0, 0);
    run_gemm128(p_zq,  Wrot_q,  p_qrf, nullptr, TT, DD, LQ,  1, 0, 0, 0);
    run_gemm128(p_zkv, Wrot_k,  p_krf, nullptr, TT, DD, LKV, 1, 0, 0, 0);
    run_gemm128(p_zq,  Wq_up,   p_q,   nullptr, TT, DD, LQ,  1, 0, 0, 0);
    run_gemm128(p_zkv, Wk_up,   p_k,   nullptr, TT, DD, LKV, 1, 0, 0, 0);
    run_gemm128(p_zkv, Wv_up,   p_v,   nullptr, TT, DD, LKV, 1, 0, 0, 0);
    rope_kernel<<<(TT * HH * ROT + 255) / 256, 256>>>();
    fattn_kernel<<<dim3(SS / 64, TB * HH), 256>>>();
    run_gemm128(p_ao, Wout, p_x1, x, TT, DD, DD, 1, 0, 0, 0);

    // ---- sublayer 2 ----
    rmsnorm_kernel<<<TT, 256>>>(p_x1, n2w, p_xn2);
    run_gemm128(p_xn2, Ws1, p_h1, nullptr, TT, 2 * FF, DD, 1, 0, 0, 0);
    swiglu_kernel<<<(TT * FF + 255) / 256, 256>>>(p_h1, p_hs, TT);
    run_gemm128(p_hs, Ws2, out, p_x1, TT, DD, FF, 1, 0, 0, 0);  // out = x1 + shared
    gate_kernel<<<TT, 256>>>(Wgate, ebias);
    top2_kernel<<<(TT + 255) / 256, 256>>>();
    select_kernel<<<NR, 1024>>>();
    gather_kernel<<<NR * CAP, 256>>>();
    run_gemm128(p_ga, Wr1, p_hr, nullptr, CAP, 2 * FF, DD, NR,
                (long long)CAP * DD, (long long)DD * 2 * FF, (long long)CAP * 2 * FF);
    swiglu_kernel<<<(NR * CAP * FF + 255) / 256, 256>>>(p_hr, p_hr2, NR * CAP);
    run_gemm128(p_hr2, Wr2, p_eo, nullptr, CAP, DD, FF, NR,
                (long long)CAP * FF, (long long)FF * DD, (long long)CAP * FF);
    scatter_kernel<<<NR * CAP, 256>>>(out);
}

// round 3
// speedup vs baseline: 2.8535x; 1.0928x over previous
#include <cuda_runtime.h>
#include <cuda_bf16.h>
#include <math.h>

// ---------------- static config ----------------
#define TB 2
#define SS 2048
#define DD 1024
#define HH 16
#define HDD 64
#define ROT 32
#define LQ 512
#define LKV 256
#define FF 1024
#define NR 7
#define CAP 585
#define TT (TB*SS)   // 4096 tokens

// ---------------- device scratch ----------------
__device__ float g_xn [TT*DD];
__device__ float g_zq [TT*LQ];
__device__ float g_zkv[TT*LKV];
__device__ float g_wqr[LQ*512];    // packed rot weights (q)
__device__ float g_wkr[LKV*512];   // packed rot weights (k)
__device__ float g_qrf[TT*512];
__device__ float g_krf[TT*512];
__device__ float g_q  [TT*DD];
__device__ float g_k  [TT*DD];
__device__ float g_v  [TT*DD];
__device__ float g_ao [TT*DD];
__device__ float g_x1 [TT*DD];
__device__ float g_xn2[TT*DD];
__device__ float g_h1 [TT*2*FF];
__device__ float g_hs [TT*FF];
__device__ float g_aff[TT*NR];
__device__ int2  g_top[TT];
__device__ int   g_selidx[NR*CAP];
__device__ float g_selw  [NR*CAP];
__device__ float g_gath[NR*CAP*DD];
__device__ float g_hr  [NR*CAP*2*FF];
__device__ float g_hr2 [NR*CAP*FF];
__device__ float g_eout[NR*CAP*DD];

// ---------------- RMSNorm ----------------
__global__ void rmsnorm_kernel(const float* __restrict__ x,
                               const float* __restrict__ w,
                               float* __restrict__ o) {
    int t = blockIdx.x;
    int tid = threadIdx.x;
    __shared__ float red[256];
    const float4* xr = (const float4*)(x + (long long)t * DD);
    float4 v = xr[tid];
    float ss = v.x*v.x + v.y*v.y + v.z*v.z + v.w*v.w;
    red[tid] = ss; __syncthreads();
    for (int off = 128; off > 0; off >>= 1) {
        if (tid < off) red[tid] += red[tid + off];
        __syncthreads();
    }
    float inv = rsqrtf(red[0] / (float)DD + 1e-6f);
    const float4* wr = (const float4*)w;
    float4 wv = wr[tid];
    float4 ov = make_float4(v.x*inv*wv.x, v.y*inv*wv.y, v.z*inv*wv.z, v.w*inv*wv.w);
    ((float4*)(o + (long long)t * DD))[tid] = ov;
}

// ---------------- SGEMM 64x64x16 (narrow N) ----------------
__global__ void sgemm_kernel(const float* __restrict__ A,
                             const float* __restrict__ B,
                             float* __restrict__ C,
                             const float* __restrict__ Add,
                             int M, int N, int K,
                             long long sA, long long sB, long long sC) {
    int z = blockIdx.z;
    A += (long long)z * sA;
    B += (long long)z * sB;
    C += (long long)z * sC;
    if (Add) Add += (long long)z * sC;

    int m0 = blockIdx.y * 64, n0 = blockIdx.x * 64;
    int tid = threadIdx.x;
    int tx = tid & 15, ty = tid >> 4;

    __shared__ __align__(16) float As[16][64];
    __shared__ __align__(16) float Bs[16][64];

    float acc[4][4];
#pragma unroll
    for (int i = 0; i < 4; i++)
#pragma unroll
        for (int j = 0; j < 4; j++) acc[i][j] = 0.f;

    int arow = tid >> 2;
    int acol = (tid & 3) * 4;
    int brow = tid >> 4;
    int bcol = (tid & 15) * 4;

    for (int k0 = 0; k0 < K; k0 += 16) {
        float4 av = make_float4(0.f, 0.f, 0.f, 0.f);
        if (m0 + arow < M)
            av = *(const float4*)&A[(long long)(m0 + arow) * K + k0 + acol];
        As[acol + 0][arow] = av.x;
        As[acol + 1][arow] = av.y;
        As[acol + 2][arow] = av.z;
        As[acol + 3][arow] = av.w;
        float4 bv = *(const float4*)&B[(long long)(k0 + brow) * N + n0 + bcol];
        *(float4*)&Bs[brow][bcol] = bv;
        __syncthreads();
#pragma unroll
        for (int kk = 0; kk < 16; kk++) {
            float4 a = *(const float4*)&As[kk][ty * 4];
            float4 b = *(const float4*)&Bs[kk][tx * 4];
            acc[0][0] += a.x*b.x; acc[0][1] += a.x*b.y; acc[0][2] += a.x*b.z; acc[0][3] += a.x*b.w;
            acc[1][0] += a.y*b.x; acc[1][1] += a.y*b.y; acc[1][2] += a.y*b.z; acc[1][3] += a.y*b.w;
            acc[2][0] += a.z*b.x; acc[2][1] += a.z*b.y; acc[2][2] += a.z*b.z; acc[2][3] += a.z*b.w;
            acc[3][0] += a.w*b.x; acc[3][1] += a.w*b.y; acc[3][2] += a.w*b.z; acc[3][3] += a.w*b.w;
        }
        __syncthreads();
    }

#pragma unroll
    for (int i = 0; i < 4; i++) {
        int row = m0 + ty * 4 + i;
        if (row < M) {
            long long off = (long long)row * N + n0 + tx * 4;
            float4 r = make_float4(acc[i][0], acc[i][1], acc[i][2], acc[i][3]);
            if (Add) {
                float4 ad = *(const float4*)&Add[off];
                r.x += ad.x; r.y += ad.y; r.z += ad.z; r.w += ad.w;
            }
            *(float4*)&C[off] = r;
        }
    }
}

// ---------------- SGEMM 128x128x16, 8x8 micro-tile, double-buffered ----------------
__global__ void __launch_bounds__(256)
sgemm128_kernel(const float* __restrict__ A,
                const float* __restrict__ B,
                float* __restrict__ C,
                const float* __restrict__ Add,
                int M, int N, int K,
                long long sA, long long sB, long long sC) {
    int z = blockIdx.z;
    A += (long long)z * sA;
    B += (long long)z * sB;
    C += (long long)z * sC;
    if (Add) Add += (long long)z * sC;

    int m0 = blockIdx.y * 128, n0 = blockIdx.x * 128;
    int tid = threadIdx.x;
    int ty = tid >> 4, tx = tid & 15;

    __shared__ __align__(16) float As[2][16][128];
    __shared__ __align__(16) float Bs[2][16][128];

    float acc[8][8];
#pragma unroll
    for (int i = 0; i < 8; i++)
#pragma unroll
        for (int j = 0; j < 8; j++) acc[i][j] = 0.f;

    int arow = tid >> 1;
    int acol = (tid & 1) * 8;
    int brow = tid >> 4;
    int bcol = (tid & 15) * 8;
    bool arowok = (m0 + arow) < M;
    const float* Ap = A + (long long)(m0 + arow) * K + acol;
    const float* Bp = B + (long long)brow * N + n0 + bcol;

    float4 av0 = make_float4(0,0,0,0), av1 = av0, bv0, bv1;
    if (arowok) {
        av0 = *(const float4*)&Ap[0];
        av1 = *(const float4*)&Ap[4];
    }
    bv0 = *(const float4*)&Bp[0];
    bv1 = *(const float4*)&Bp[4];

    {
        As[0][acol + 0][arow] = av0.x; As[0][acol + 1][arow] = av0.y;
        As[0][acol + 2][arow] = av0.z; As[0][acol + 3][arow] = av0.w;
        As[0][acol + 4][arow] = av1.x; As[0][acol + 5][arow] = av1.y;
        As[0][acol + 6][arow] = av1.z; As[0][acol + 7][arow] = av1.w;
        *(float4*)&Bs[0][brow][bcol] = bv0;
        *(float4*)&Bs[0][brow][bcol + 4] = bv1;
    }
    __syncthreads();

    int nk = K >> 4;
    for (int t = 0; t < nk; t++) {
        int cur = t & 1;
        if (t + 1 < nk) {
            const float* Apn = Ap + (t + 1) * 16;
            const float* Bpn = Bp + (long long)(t + 1) * 16 * N;
            if (arowok) {
                av0 = *(const float4*)&Apn[0];
                av1 = *(const float4*)&Apn[4];
            }
            bv0 = *(const float4*)&Bpn[0];
            bv1 = *(const float4*)&Bpn[4];
        }
#pragma unroll
        for (int kk = 0; kk < 16; kk++) {
            float a[8], b[8];
            *(float4*)&a[0] = *(const float4*)&As[cur][kk][ty * 4];
            *(float4*)&a[4] = *(const float4*)&As[cur][kk][64 + ty * 4];
            *(float4*)&b[0] = *(const float4*)&Bs[cur][kk][tx * 4];
            *(float4*)&b[4] = *(const float4*)&Bs[cur][kk][64 + tx * 4];
#pragma unroll
            for (int i = 0; i < 8; i++)
#pragma unroll
                for (int j = 0; j < 8; j++)
                    acc[i][j] += a[i] * b[j];
        }
        if (t + 1 < nk) {
            int nxt = cur ^ 1;
            As[nxt][acol + 0][arow] = av0.x; As[nxt][acol + 1][arow] = av0.y;
            As[nxt][acol + 2][arow] = av0.z; As[nxt][acol + 3][arow] = av0.w;
            As[nxt][acol + 4][arow] = av1.x; As[nxt][acol + 5][arow] = av1.y;
            As[nxt][acol + 6][arow] = av1.z; As[nxt][acol + 7][arow] = av1.w;
            *(float4*)&Bs[nxt][brow][bcol] = bv0;
            *(float4*)&Bs[nxt][brow][bcol + 4] = bv1;
        }
        __syncthreads();
    }

#pragma unroll
    for (int hi = 0; hi < 2; hi++) {
#pragma unroll
        for (int ii = 0; ii < 4; ii++) {
            int row = m0 + hi * 64 + ty * 4 + ii;
            if (row >= M) continue;
#pragma unroll
            for (int hj = 0; hj < 2; hj++) {
                long long off = (long long)row * N + n0 + hj * 64 + tx * 4;
                int ai = hi * 4 + ii;
                float4 r = make_float4(acc[ai][hj*4+0], acc[ai][hj*4+1],
                                       acc[ai][hj*4+2], acc[ai][hj*4+3]);
                if (Add) {
                    float4 ad = *(const float4*)&Add[off];
                    r.x += ad.x; r.y += ad.y; r.z += ad.z; r.w += ad.w;
                }
                *(float4*)&C[off] = r;
            }
        }
    }
}

// ---------------- pack rot weights: keep first ROT of each head's 2*ROT ----------------
__global__ void packrot_kernel(const float* __restrict__ Wq,
                               const float* __restrict__ Wk) {
    int idx = blockIdx.x * 256 + threadIdx.x;
    if (idx < LQ * 512) {
        int r = idx >> 9, c = idx & 511;
        int h = c >> 5, j = c & 31;
        g_wqr[idx] = Wq[r * 1024 + h * 64 + j];
    }
    if (idx < LKV * 512) {
        int r = idx >> 9, c = idx & 511;
        int h = c >> 5, j = c & 31;
        g_wkr[idx] = Wk[r * 1024 + h * 64 + j];
    }
}

// ---------------- RoPE: fill rotary half of q/k (packed rot layout) ----------------
__global__ void rope_kernel() {
    int idx = blockIdx.x * blockDim.x + threadIdx.x;    // TT*HH*ROT = 2M
    if (idx >= TT * HH * ROT) return;
    int j = idx & (ROT - 1);
    int h = (idx >> 5) & (HH - 1);
    int t = idx >> 9;
    int s = t & (SS - 1);
    int i = j & 15;
    float invf = __expf(-9.210340371976184f * (float)i / 16.f);
    float ang = (float)s * invf;
    float sn, c;
    sincosf(ang, &sn, &c);
    long long pb = (long long)t * 512 + h * 32;
    float qr = g_qrf[pb + j];
    float kr = g_krf[pb + j];
    float qo = (j < 16) ? -g_qrf[pb + j + 16] : g_qrf[pb + j - 16];
    float ko = (j < 16) ? -g_krf[pb + j + 16] : g_krf[pb + j - 16];
    long long base = (long long)t * DD + h * HDD;
    g_q[base + 32 + j] = qr * c + qo * sn;
    g_k[base + 32 + j] = kr * c + ko * sn;
}

// ---------------- flash attention: 128 queries x 64 keys, 8x4 micro ----------------
__global__ void __launch_bounds__(256) fattn_kernel() {
    extern __shared__ float sm[];
    float (*Qs)[128] = (float(*)[128])sm;                         // [64][128]
    float (*Ks)[64]  = (float(*)[64])(sm + 64 * 128);             // [64][64]
    float (*Vs)[64]  = (float(*)[64])(sm + 64 * 128 + 64 * 64);   // [64][64]
    float (*Ps)[64]  = (float(*)[64])(sm + 64 * 128 + 2 * 64 * 64); // [128][64]

    const int q0 = blockIdx.x * 128;
    const int bh = blockIdx.y;
    const int b = bh >> 4, h = bh & 15;
    const int tid = threadIdx.x;
    const int ty = tid >> 4, tx = tid & 15;

    const float* Qg = g_q + ((long long)(b * SS + q0)) * DD + h * HDD;
    const float* Kg = g_k + ((long long)b * SS) * DD + h * HDD;
    const float* Vg = g_v + ((long long)b * SS) * DD + h * HDD;

    {
        int r = tid >> 1;
        int c0 = (tid & 1) * 32;
#pragma unroll
        for (int u = 0; u < 8; u++) {
            float4 v = *(const float4*)&Qg[(long long)r * DD + c0 + u * 4];
            Qs[c0 + u*4 + 0][r] = v.x;
            Qs[c0 + u*4 + 1][r] = v.y;
            Qs[c0 + u*4 + 2][r] = v.z;
            Qs[c0 + u*4 + 3][r] = v.w;
        }
    }

    float O[8][4];
#pragma unroll
    for (int i = 0; i < 8; i++)
#pragma unroll
        for (int j = 0; j < 4; j++) O[i][j] = 0.f;
    float m[8], l[8];
#pragma unroll
    for (int i = 0; i < 8; i++) { m[i] = -1e30f; l[i] = 0.f; }

    for (int k0 = 0; k0 < q0 + 128; k0 += 64) {
        __syncthreads();   // prev PV done; Ks/Vs free
        {
            int r = tid >> 2;
            int c0 = (tid & 3) * 16;
#pragma unroll
            for (int u = 0; u < 4; u++) {
                float4 kv = *(const float4*)&Kg[(long long)(k0 + r) * DD + c0 + u * 4];
                Ks[c0 + u*4 + 0][r] = kv.x;
                Ks[c0 + u*4 + 1][r] = kv.y;
                Ks[c0 + u*4 + 2][r] = kv.z;
                Ks[c0 + u*4 + 3][r] = kv.w;
                *(float4*)&Vs[r][c0 + u*4] =
                    *(const float4*)&Vg[(long long)(k0 + r) * DD + c0 + u * 4];
            }
        }
        __syncthreads();

        float s[8][4];
#pragma unroll
        for (int i = 0; i < 8; i++)
#pragma unroll
            for (int j = 0; j < 4; j++) s[i][j] = 0.f;
#pragma unroll 8
        for (int d = 0; d < 64; d++) {
            float a[8], bb[4];
            *(float4*)&a[0] = *(const float4*)&Qs[d][ty * 8];
            *(float4*)&a[4] = *(const float4*)&Qs[d][ty * 8 + 4];
            *(float4*)&bb[0] = *(const float4*)&Ks[d][tx * 4];
#pragma unroll
            for (int i = 0; i < 8; i++)
#pragma unroll
                for (int j = 0; j < 4; j++)
                    s[i][j] += a[i] * bb[j];
        }

        if (k0 + 63 > q0) {
#pragma unroll
            for (int i = 0; i < 8; i++)
#pragma unroll
                for (int j = 0; j < 4; j++)
                    s[i][j] = (k0 + tx*4 + j <= q0 + ty*8 + i) ? s[i][j] * 0.125f : -1e30f;
        } else {
#pragma unroll
            for (int i = 0; i < 8; i++)
#pragma unroll
                for (int j = 0; j < 4; j++) s[i][j] *= 0.125f;
        }

#pragma unroll
        for (int i = 0; i < 8; i++) {
            float mx = fmaxf(fmaxf(s[i][0], s[i][1]), fmaxf(s[i][2], s[i][3]));
#pragma unroll
            for (int off = 1; off < 16; off <<= 1)
                mx = fmaxf(mx, __shfl_xor_sync(0xffffffffu, mx, off));
            float mn = fmaxf(m[i], mx);
            float corr = __expf(m[i] - mn);
            float p0 = __expf(s[i][0] - mn);
            float p1 = __expf(s[i][1] - mn);
            float p2 = __expf(s[i][2] - mn);
            float p3 = __expf(s[i][3] - mn);
            *(float4*)&Ps[ty*8 + i][tx*4] = make_float4(p0, p1, p2, p3);
            float sum = p0 + p1 + p2 + p3;
#pragma unroll
            for (int off = 1; off < 16; off <<= 1)
                sum += __shfl_xor_sync(0xffffffffu, sum, off);
            l[i] = l[i] * corr + sum;
            m[i] = mn;
            O[i][0] *= corr; O[i][1] *= corr; O[i][2] *= corr; O[i][3] *= corr;
        }
        __syncthreads();   // P visible

#pragma unroll 8
        for (int c = 0; c < 64; c++) {
            float bb[4];
            *(float4*)&bb[0] = *(const float4*)&Vs[c][tx * 4];
#pragma unroll
            for (int i = 0; i < 8; i++) {
                float a = Ps[ty*8 + i][c];
                O[i][0] += a*bb[0]; O[i][1] += a*bb[1];
                O[i][2] += a*bb[2]; O[i][3] += a*bb[3];
            }
        }
    }

    float* Og = g_ao + ((long long)(b * SS + q0)) * DD + h * HDD;
#pragma unroll
    for (int i = 0; i < 8; i++) {
        float inv = 1.f / l[i];
        float4 o = make_float4(O[i][0]*inv, O[i][1]*inv, O[i][2]*inv, O[i][3]*inv);
        *(float4*)&Og[(long long)(ty*8 + i) * DD + tx * 4] = o;
    }
}

// ---------------- SwiGLU ----------------
__global__ void swiglu_kernel(const float* __restrict__ in,
                              float* __restrict__ out, int rows) {
    long long i = (long long)blockIdx.x * blockDim.x + threadIdx.x;
    if (i >= (long long)rows * FF) return;
    long long r = i / FF;
    int f = (int)(i - r * FF);
    float a = in[r * 2 * FF + f];
    float bv = in[r * 2 * FF + FF + f];
    out[i] = a * (bv / (1.f + __expf(-bv)));
}

// ---------------- gating ----------------
__global__ void gate_kernel(const float* __restrict__ Wg,
                            const float* __restrict__ bias) {
    int t = blockIdx.x;
    int w = threadIdx.x >> 5, lane = threadIdx.x & 31;
    if (w >= NR) return;
    float s = 0.f;
    const float* xr = g_xn2 + (long long)t * DD;
    for (int i = lane; i < DD; i += 32) s += xr[i] * Wg[i * NR + w];
#pragma unroll
    for (int off = 16; off > 0; off >>= 1)
        s += __shfl_down_sync(0xffffffff, s, off);
    if (lane == 0)
        g_aff[t * NR + w] = 1.f / (1.f + __expf(-(s + bias[w])));
}

// ---------------- per-token top-2 ----------------
__global__ void top2_kernel() {
    int t = blockIdx.x * blockDim.x + threadIdx.x;
    if (t >= TT) return;
    float a[NR];
#pragma unroll
    for (int e = 0; e < NR; e++) a[e] = g_aff[t * NR + e];
    int e1 = 0; float b1 = a[0];
#pragma unroll
    for (int e = 1; e < NR; e++) if (a[e] > b1) { b1 = a[e]; e1 = e; }
    int e2 = -1; float b2 = -1.f;
#pragma unroll
    for (int e = 0; e < NR; e++) if (e != e1 && a[e] > b2) { b2 = a[e]; e2 = e; }
    g_top[t] = make_int2(e1, e2);
}

// ---------------- per-expert capacity selection ----------------
__global__ void select_kernel() {
    __shared__ unsigned long long keys[TT];
    int e = blockIdx.x;
    int tid = threadIdx.x;
    for (int i = tid; i < TT; i += 1024) {
        int2 tp = g_top[i];
        unsigned hi;
        if (tp.x == e || tp.y == e) {
            unsigned ev = __float_as_uint(g_aff[i * NR + e]);
            hi = ~ev;
        } else {
            hi = 0xFFFFFFFFu;
        }
        keys[i] = ((unsigned long long)hi << 32) | (unsigned)i;
    }
    __syncthreads();
    for (int ksz = 2; ksz <= TT; ksz <<= 1) {
        for (int j = ksz >> 1; j > 0; j >>= 1) {
            for (int base = tid; base < TT / 2; base += 1024) {
                int i = ((base & ~(j - 1)) << 1) | (base & (j - 1));
                int p = i + j;
                bool up = ((i & ksz) == 0);
                unsigned long long a = keys[i], b2 = keys[p];
                if ((a > b2) == up) { keys[i] = b2; keys[p] = a; }
            }
            __syncthreads();
        }
    }
    for (int c = tid; c < CAP; c += 1024) {
        unsigned long long kk = keys[c];
        int idx = (int)(kk & 0xFFFFFFFFu);
        bool valid = (unsigned)(kk >> 32) != 0xFFFFFFFFu;
        g_selidx[e * CAP + c] = idx;
        g_selw[e * CAP + c] = valid ? g_aff[idx * NR + e] : 0.f;
    }
}

// ---------------- gather ----------------
__global__ void gather_kernel() {
    int row = blockIdx.x;
    int t = g_selidx[row];
    int i = threadIdx.x * 4;
    float4 v = *(const float4*)&g_xn2[(long long)t * DD + i];
    *(float4*)&g_gath[(long long)row * DD + i] = v;
}

// ---------------- scatter-add ----------------
__global__ void scatter_kernel(float* __restrict__ out) {
    int row = blockIdx.x;
    float w = g_selw[row];
    if (w == 0.f) return;
    int t = g_selidx[row];
    int i = threadIdx.x * 4;
    const float* src = &g_eout[(long long)row * DD + i];
    float* dst = &out[(long long)t * DD + i];
#pragma unroll
    for (int j = 0; j < 4; j++) atomicAdd(dst + j, src[j] * w);
}

// ---------------- host helpers ----------------
static float* sym(const void* s) {
    void* p = nullptr;
    cudaGetSymbolAddress(&p, (const void*)s);
    return (float*)p;
}

static void run_gemm64(const float* A, const float* B, float* C, const float* Add,
                       int M, int N, int K, int batch,
                       long long sA, long long sB, long long sC) {
    dim3 grid((N + 63) / 64, (M + 63) / 64, batch);
    sgemm_kernel<<<grid, 256>>>(A, B, C, Add, M, N, K, sA, sB, sC);
}

static void run_gemm128(const float* A, const float* B, float* C, const float* Add,
                        int M, int N, int K, int batch,
                        long long sA, long long sB, long long sC) {
    dim3 grid((N + 127) / 128, (M + 127) / 128, batch);
    sgemm128_kernel<<<grid, 256>>>(A, B, C, Add, M, N, K, sA, sB, sC);
}

#define ATT_SMEM (98304)

extern "C" void kernel_launch(void* const* d_in, const int* in_sizes, int n_in,
                              void* d_out, int out_size) {
    const float* x       = (const float*)d_in[0];
    const float* Wq_lat  = (const float*)d_in[2];
    const float* Wkv_lat = (const float*)d_in[3];
    const float* Wrot_q  = (const float*)d_in[4];
    const float* Wrot_k  = (const float*)d_in[5];
    const float* Wq_up   = (const float*)d_in[6];
    const float* Wk_up   = (const float*)d_in[7];
    const float* Wv_up   = (const float*)d_in[8];
    const float* Wout    = (const float*)d_in[9];
    const float* n1w     = (const float*)d_in[10];
    const float* n2w     = (const float*)d_in[11];
    const float* Ws1     = (const float*)d_in[12];
    const float* Ws2     = (const float*)d_in[13];
    const float* Wr1     = (const float*)d_in[14];
    const float* Wr2     = (const float*)d_in[15];
    const float* Wgate   = (const float*)d_in[16];
    const float* ebias   = (const float*)d_in[17];
    float* out = (float*)d_out;

    float* p_xn  = sym(&g_xn);
    float* p_zq  = sym(&g_zq);
    float* p_zkv = sym(&g_zkv);
    float* p_wqr = sym(&g_wqr);
    float* p_wkr = sym(&g_wkr);
    float* p_qrf = sym(&g_qrf);
    float* p_krf = sym(&g_krf);
    float* p_q   = sym(&g_q);
    float* p_k   = sym(&g_k);
    float* p_v   = sym(&g_v);
    float* p_ao  = sym(&g_ao);
    float* p_x1  = sym(&g_x1);
    float* p_xn2 = sym(&g_xn2);
    float* p_h1  = sym(&g_h1);
    float* p_hs  = sym(&g_hs);
    float* p_ga  = sym(&g_gath);
    float* p_hr  = sym(&g_hr);
    float* p_hr2 = sym(&g_hr2);
    float* p_eo  = sym(&g_eout);

    cudaFuncSetAttribute(fattn_kernel, cudaFuncAttributeMaxDynamicSharedMemorySize, ATT_SMEM);

    // ---- sublayer 1 ----
    rmsnorm_kernel<<<TT, 256>>>(x, n1w, p_xn);
    packrot_kernel<<<(LQ * 512 + 255) / 256, 256>>>(Wrot_q, Wrot_k);
    run_gemm128(p_xn,  Wq_lat,  p_zq,  nullptr, TT, LQ,  DD, 1, 0, 0, 0);
    run_gemm64 (p_xn,  Wkv_lat, p_zkv, nullptr, TT, LKV, DD, 1, 0, 0, 0);
    run_gemm128(p_zq,  p_wqr,   p_qrf, nullptr, TT, 512, LQ,  1, 0, 0, 0);
    run_gemm128(p_zkv, p_wkr,   p_krf, nullptr, TT, 512, LKV, 1, 0, 0, 0);
    run_gemm128(p_zq,  Wq_up,   p_q,   nullptr, TT, DD, LQ,  1, 0, 0, 0);
    run_gemm128(p_zkv, Wk_up,   p_k,   nullptr, TT, DD, LKV, 1, 0, 0, 0);
    run_gemm128(p_zkv, Wv_up,   p_v,   nullptr, TT, DD, LKV, 1, 0, 0, 0);
    rope_kernel<<<(TT * HH * ROT + 255) / 256, 256>>>();
    fattn_kernel<<<dim3(SS / 128, TB * HH), 256, ATT_SMEM>>>();
    run_gemm128(p_ao, Wout, p_x1, x, TT, DD, DD, 1, 0, 0, 0);

    // ---- sublayer 2 ----
    rmsnorm_kernel<<<TT, 256>>>(p_x1, n2w, p_xn2);
    run_gemm128(p_xn2, Ws1, p_h1, nullptr, TT, 2 * FF, DD, 1, 0, 0, 0);
    swiglu_kernel<<<(TT * FF + 255) / 256, 256>>>(p_h1, p_hs, TT);
    run_gemm128(p_hs, Ws2, out, p_x1, TT, DD, FF, 1, 0, 0, 0);
    gate_kernel<<<TT, 256>>>(Wgate, ebias);
    top2_kernel<<<(TT + 255) / 256, 256>>>();
    select_kernel<<<NR, 1024>>>();
    gather_kernel<<<NR * CAP, 256>>>();
    run_gemm128(p_ga, Wr1, p_hr, nullptr, CAP, 2 * FF, DD, NR,
                (long long)CAP * DD, (long long)DD * 2 * FF, (long long)CAP * 2 * FF);
    swiglu_kernel<<<(NR * CAP * FF + 255) / 256, 256>>>(p_hr, p_hr2, NR * CAP);
    run_gemm128(p_hr2, Wr2, p_eo, nullptr, CAP, DD, FF, NR,
                (long long)CAP * FF, (long long)FF * DD, (long long)CAP * FF);
    scatter_kernel<<<NR * CAP, 256>>>(out);
}

// round 4
// speedup vs baseline: 3.5582x; 1.2470x over previous
#include <cuda_runtime.h>
#include <cuda_bf16.h>
#include <math.h>

// ---------------- static config ----------------
#define TB 2
#define SS 2048
#define DD 1024
#define HH 16
#define HDD 64
#define ROT 32
#define LQ 512
#define LKV 256
#define FF 1024
#define NR 7
#define CAP 585
#define TT (TB*SS)   // 4096 tokens

// ---------------- device scratch ----------------
__device__ float g_xn [TT*DD];
__device__ float g_wcat[DD*768];   // Wq_lat || Wkv_lat
__device__ float g_z  [TT*768];    // zq (0..511) | zkv (512..767)
__device__ float g_wqr[LQ*512];    // packed rot weights (q)
__device__ float g_wkr[LKV*512];   // packed rot weights (k)
__device__ float g_qrf[TT*512];
__device__ float g_krf[TT*512];
__device__ float g_q  [TT*DD];
__device__ float g_k  [TT*DD];
__device__ float g_v  [TT*DD];
__device__ float g_ao [TT*DD];
__device__ float g_x1 [TT*DD];
__device__ float g_xn2[TT*DD];
__device__ float g_h1 [TT*2*FF];
__device__ float g_hs [TT*FF];
__device__ float g_aff[TT*NR];
__device__ int2  g_top[TT];
__device__ int   g_selidx[NR*CAP];
__device__ float g_selw  [NR*CAP];
__device__ float g_gath[NR*CAP*DD];
__device__ float g_hr  [NR*CAP*2*FF];
__device__ float g_hr2 [NR*CAP*FF];
__device__ float g_eout[NR*CAP*DD];

// ---------------- helpers ----------------
__device__ __forceinline__ unsigned f2tf32(float f) {
    unsigned u;
    asm("cvt.rna.tf32.f32 %0, %1;" : "=r"(u) : "f"(f));
    return u;
}

__device__ __forceinline__ void mma_tf32(float* c, const unsigned* a, const unsigned* b) {
    asm volatile(
        "mma.sync.aligned.m16n8k8.row.col.f32.tf32.tf32.f32 "
        "{%0,%1,%2,%3}, {%4,%5,%6,%7}, {%8,%9}, {%0,%1,%2,%3};"
        : "+f"(c[0]), "+f"(c[1]), "+f"(c[2]), "+f"(c[3])
        : "r"(a[0]), "r"(a[1]), "r"(a[2]), "r"(a[3]), "r"(b[0]), "r"(b[1]));
}

// ---------------- RMSNorm ----------------
__global__ void rmsnorm_kernel(const float* __restrict__ x,
                               const float* __restrict__ w,
                               float* __restrict__ o) {
    int t = blockIdx.x;
    int tid = threadIdx.x;
    __shared__ float red[256];
    const float4* xr = (const float4*)(x + (long long)t * DD);
    float4 v = xr[tid];
    float ss = v.x*v.x + v.y*v.y + v.z*v.z + v.w*v.w;
    red[tid] = ss; __syncthreads();
    for (int off = 128; off > 0; off >>= 1) {
        if (tid < off) red[tid] += red[tid + off];
        __syncthreads();
    }
    float inv = rsqrtf(red[0] / (float)DD + 1e-6f);
    const float4* wr = (const float4*)w;
    float4 wv = wr[tid];
    float4 ov = make_float4(v.x*inv*wv.x, v.y*inv*wv.y, v.z*inv*wv.z, v.w*inv*wv.w);
    ((float4*)(o + (long long)t * DD))[tid] = ov;
}

// ---------------- SGEMM 128x128x16, 8x8 micro-tile, double-buffered (fp32) ----------------
__global__ void __launch_bounds__(256)
sgemm128_kernel(const float* __restrict__ A,
                const float* __restrict__ B,
                float* __restrict__ C,
                const float* __restrict__ Add,
                int M, int N, int K, int lda,
                long long sA, long long sB, long long sC) {
    int z = blockIdx.z;
    A += (long long)z * sA;
    B += (long long)z * sB;
    C += (long long)z * sC;
    if (Add) Add += (long long)z * sC;

    int m0 = blockIdx.y * 128, n0 = blockIdx.x * 128;
    int tid = threadIdx.x;
    int ty = tid >> 4, tx = tid & 15;

    __shared__ __align__(16) float As[2][16][128];
    __shared__ __align__(16) float Bs[2][16][128];

    float acc[8][8];
#pragma unroll
    for (int i = 0; i < 8; i++)
#pragma unroll
        for (int j = 0; j < 8; j++) acc[i][j] = 0.f;

    int arow = tid >> 1;
    int acol = (tid & 1) * 8;
    int brow = tid >> 4;
    int bcol = (tid & 15) * 8;
    bool arowok = (m0 + arow) < M;
    const float* Ap = A + (long long)(m0 + arow) * lda + acol;
    const float* Bp = B + (long long)brow * N + n0 + bcol;

    float4 av0 = make_float4(0,0,0,0), av1 = av0, bv0, bv1;
    if (arowok) {
        av0 = *(const float4*)&Ap[0];
        av1 = *(const float4*)&Ap[4];
    }
    bv0 = *(const float4*)&Bp[0];
    bv1 = *(const float4*)&Bp[4];

    {
        As[0][acol + 0][arow] = av0.x; As[0][acol + 1][arow] = av0.y;
        As[0][acol + 2][arow] = av0.z; As[0][acol + 3][arow] = av0.w;
        As[0][acol + 4][arow] = av1.x; As[0][acol + 5][arow] = av1.y;
        As[0][acol + 6][arow] = av1.z; As[0][acol + 7][arow] = av1.w;
        *(float4*)&Bs[0][brow][bcol] = bv0;
        *(float4*)&Bs[0][brow][bcol + 4] = bv1;
    }
    __syncthreads();

    int nk = K >> 4;
    for (int t = 0; t < nk; t++) {
        int cur = t & 1;
        if (t + 1 < nk) {
            const float* Apn = Ap + (t + 1) * 16;
            const float* Bpn = Bp + (long long)(t + 1) * 16 * N;
            if (arowok) {
                av0 = *(const float4*)&Apn[0];
                av1 = *(const float4*)&Apn[4];
            }
            bv0 = *(const float4*)&Bpn[0];
            bv1 = *(const float4*)&Bpn[4];
        }
#pragma unroll
        for (int kk = 0; kk < 16; kk++) {
            float a[8], b[8];
            *(float4*)&a[0] = *(const float4*)&As[cur][kk][ty * 4];
            *(float4*)&a[4] = *(const float4*)&As[cur][kk][64 + ty * 4];
            *(float4*)&b[0] = *(const float4*)&Bs[cur][kk][tx * 4];
            *(float4*)&b[4] = *(const float4*)&Bs[cur][kk][64 + tx * 4];
#pragma unroll
            for (int i = 0; i < 8; i++)
#pragma unroll
                for (int j = 0; j < 8; j++)
                    acc[i][j] += a[i] * b[j];
        }
        if (t + 1 < nk) {
            int nxt = cur ^ 1;
            As[nxt][acol + 0][arow] = av0.x; As[nxt][acol + 1][arow] = av0.y;
            As[nxt][acol + 2][arow] = av0.z; As[nxt][acol + 3][arow] = av0.w;
            As[nxt][acol + 4][arow] = av1.x; As[nxt][acol + 5][arow] = av1.y;
            As[nxt][acol + 6][arow] = av1.z; As[nxt][acol + 7][arow] = av1.w;
            *(float4*)&Bs[nxt][brow][bcol] = bv0;
            *(float4*)&Bs[nxt][brow][bcol + 4] = bv1;
        }
        __syncthreads();
    }

#pragma unroll
    for (int hi = 0; hi < 2; hi++) {
#pragma unroll
        for (int ii = 0; ii < 4; ii++) {
            int row = m0 + hi * 64 + ty * 4 + ii;
            if (row >= M) continue;
#pragma unroll
            for (int hj = 0; hj < 2; hj++) {
                long long off = (long long)row * N + n0 + hj * 64 + tx * 4;
                int ai = hi * 4 + ii;
                float4 r = make_float4(acc[ai][hj*4+0], acc[ai][hj*4+1],
                                       acc[ai][hj*4+2], acc[ai][hj*4+3]);
                if (Add) {
                    float4 ad = *(const float4*)&Add[off];
                    r.x += ad.x; r.y += ad.y; r.z += ad.z; r.w += ad.w;
                }
                *(float4*)&C[off] = r;
            }
        }
    }
}

// ---------------- TF32 tensor-core GEMM 128x128x16 ----------------
// 8 warps: warp grid 2(m) x 4(n), warp tile 64x32, mma m16n8k8.
__global__ void __launch_bounds__(256)
tf32gemm_kernel(const float* __restrict__ A,
                const float* __restrict__ B,
                float* __restrict__ C,
                const float* __restrict__ Add,
                int M, int N, int K,
                long long sA, long long sB, long long sC) {
    int z = blockIdx.z;
    A += (long long)z * sA;
    B += (long long)z * sB;
    C += (long long)z * sC;
    if (Add) Add += (long long)z * sC;

    const int m0 = blockIdx.y * 128, n0 = blockIdx.x * 128;
    const int tid = threadIdx.x;
    const int w = tid >> 5, lane = tid & 31;
    const int wm = (w >> 2) * 64;        // 0 or 64
    const int wn = (w & 3) * 32;         // 0,32,64,96
    const int gr = lane >> 2, c4 = lane & 3;

    __shared__ float As[2][16][136];
    __shared__ float Bs[2][16][136];

    float acc[4][4][4];
#pragma unroll
    for (int i = 0; i < 4; i++)
#pragma unroll
        for (int j = 0; j < 4; j++)
#pragma unroll
            for (int r = 0; r < 4; r++) acc[i][j][r] = 0.f;

    const int arow = tid >> 1;
    const int acol = (tid & 1) * 8;
    const int brow = tid >> 4;
    const int bcol = (tid & 15) * 8;
    const bool arowok = (m0 + arow) < M;
    const float* Ap = A + (long long)(m0 + arow) * K + acol;
    const float* Bp = B + (long long)brow * N + n0 + bcol;

    float ar[8], br[8];
#pragma unroll
    for (int j = 0; j < 8; j++) { ar[j] = 0.f; }
    if (arowok) {
        float4 a0 = *(const float4*)&Ap[0];
        float4 a1 = *(const float4*)&Ap[4];
        ar[0]=a0.x; ar[1]=a0.y; ar[2]=a0.z; ar[3]=a0.w;
        ar[4]=a1.x; ar[5]=a1.y; ar[6]=a1.z; ar[7]=a1.w;
    }
    {
        float4 b0 = *(const float4*)&Bp[0];
        float4 b1 = *(const float4*)&Bp[4];
        br[0]=b0.x; br[1]=b0.y; br[2]=b0.z; br[3]=b0.w;
        br[4]=b1.x; br[5]=b1.y; br[6]=b1.z; br[7]=b1.w;
    }
#pragma unroll
    for (int j = 0; j < 8; j++) {
        As[0][acol + j][arow] = __uint_as_float(f2tf32(ar[j]));
        Bs[0][brow][bcol + j] = __uint_as_float(f2tf32(br[j]));
    }
    __syncthreads();

    const int nk = K >> 4;
    for (int t = 0; t < nk; t++) {
        int cur = t & 1;
        if (t + 1 < nk) {
            const float* Apn = Ap + (t + 1) * 16;
            const float* Bpn = Bp + (long long)(t + 1) * 16 * N;
            if (arowok) {
                float4 a0 = *(const float4*)&Apn[0];
                float4 a1 = *(const float4*)&Apn[4];
                ar[0]=a0.x; ar[1]=a0.y; ar[2]=a0.z; ar[3]=a0.w;
                ar[4]=a1.x; ar[5]=a1.y; ar[6]=a1.z; ar[7]=a1.w;
            }
            float4 b0 = *(const float4*)&Bpn[0];
            float4 b1 = *(const float4*)&Bpn[4];
            br[0]=b0.x; br[1]=b0.y; br[2]=b0.z; br[3]=b0.w;
            br[4]=b1.x; br[5]=b1.y; br[6]=b1.z; br[7]=b1.w;
        }
#pragma unroll
        for (int ks = 0; ks < 16; ks += 8) {
            unsigned af[4][4], bf[4][2];
#pragma unroll
            for (int mf = 0; mf < 4; mf++) {
                int am = wm + mf * 16;
                af[mf][0] = __float_as_uint(As[cur][ks + c4    ][am + gr    ]);
                af[mf][1] = __float_as_uint(As[cur][ks + c4    ][am + gr + 8]);
                af[mf][2] = __float_as_uint(As[cur][ks + c4 + 4][am + gr    ]);
                af[mf][3] = __float_as_uint(As[cur][ks + c4 + 4][am + gr + 8]);
            }
#pragma unroll
            for (int nf = 0; nf < 4; nf++) {
                int bn = wn + nf * 8;
                bf[nf][0] = __float_as_uint(Bs[cur][ks + c4    ][bn + gr]);
                bf[nf][1] = __float_as_uint(Bs[cur][ks + c4 + 4][bn + gr]);
            }
#pragma unroll
            for (int mf = 0; mf < 4; mf++)
#pragma unroll
                for (int nf = 0; nf < 4; nf++)
                    mma_tf32(acc[mf][nf], af[mf], bf[nf]);
        }
        if (t + 1 < nk) {
            int nxt = cur ^ 1;
#pragma unroll
            for (int j = 0; j < 8; j++) {
                As[nxt][acol + j][arow] = __uint_as_float(f2tf32(ar[j]));
                Bs[nxt][brow][bcol + j] = __uint_as_float(f2tf32(br[j]));
            }
        }
        __syncthreads();
    }

    // writeback
#pragma unroll
    for (int mf = 0; mf < 4; mf++) {
        int r0 = m0 + wm + mf * 16 + gr;
        int r1 = r0 + 8;
#pragma unroll
        for (int nf = 0; nf < 4; nf++) {
            int col = n0 + wn + nf * 8 + c4 * 2;
            if (r0 < M) {
                float2 v = make_float2(acc[mf][nf][0], acc[mf][nf][1]);
                if (Add) {
                    float2 ad = *(const float2*)&Add[(long long)r0 * N + col];
                    v.x += ad.x; v.y += ad.y;
                }
                *(float2*)&C[(long long)r0 * N + col] = v;
            }
            if (r1 < M) {
                float2 v = make_float2(acc[mf][nf][2], acc[mf][nf][3]);
                if (Add) {
                    float2 ad = *(const float2*)&Add[(long long)r1 * N + col];
                    v.x += ad.x; v.y += ad.y;
                }
                *(float2*)&C[(long long)r1 * N + col] = v;
            }
        }
    }
}

// ---------------- pack Wq_lat || Wkv_lat ----------------
__global__ void packcat_kernel(const float* __restrict__ Wq,
                               const float* __restrict__ Wkv) {
    int idx = blockIdx.x * 256 + threadIdx.x;
    if (idx >= DD * 768) return;
    int r = idx / 768, c = idx % 768;
    g_wcat[idx] = (c < 512) ? Wq[r * 512 + c] : Wkv[r * 256 + (c - 512)];
}

// ---------------- pack rot weights: keep first ROT of each head's 2*ROT ----------------
__global__ void packrot_kernel(const float* __restrict__ Wq,
                               const float* __restrict__ Wk) {
    int idx = blockIdx.x * 256 + threadIdx.x;
    if (idx < LQ * 512) {
        int r = idx >> 9, c = idx & 511;
        int h = c >> 5, j = c & 31;
        g_wqr[idx] = Wq[r * 1024 + h * 64 + j];
    }
    if (idx < LKV * 512) {
        int r = idx >> 9, c = idx & 511;
        int h = c >> 5, j = c & 31;
        g_wkr[idx] = Wk[r * 1024 + h * 64 + j];
    }
}

// ---------------- RoPE ----------------
__global__ void rope_kernel() {
    int idx = blockIdx.x * blockDim.x + threadIdx.x;
    if (idx >= TT * HH * ROT) return;
    int j = idx & (ROT - 1);
    int h = (idx >> 5) & (HH - 1);
    int t = idx >> 9;
    int s = t & (SS - 1);
    int i = j & 15;
    float invf = __expf(-9.210340371976184f * (float)i / 16.f);
    float ang = (float)s * invf;
    float sn, c;
    sincosf(ang, &sn, &c);
    long long pb = (long long)t * 512 + h * 32;
    float qr = g_qrf[pb + j];
    float kr = g_krf[pb + j];
    float qo = (j < 16) ? -g_qrf[pb + j + 16] : g_qrf[pb + j - 16];
    float ko = (j < 16) ? -g_krf[pb + j + 16] : g_krf[pb + j - 16];
    long long base = (long long)t * DD + h * HDD;
    g_q[base + 32 + j] = qr * c + qo * sn;
    g_k[base + 32 + j] = kr * c + ko * sn;
}

// ---------------- flash attention: 128 queries x 64 keys, 8x4 micro ----------------
__global__ void __launch_bounds__(256) fattn_kernel() {
    extern __shared__ float sm[];
    float (*Qs)[128] = (float(*)[128])sm;
    float (*Ks)[64]  = (float(*)[64])(sm + 64 * 128);
    float (*Vs)[64]  = (float(*)[64])(sm + 64 * 128 + 64 * 64);
    float (*Ps)[64]  = (float(*)[64])(sm + 64 * 128 + 2 * 64 * 64);

    const int q0 = blockIdx.x * 128;
    const int bh = blockIdx.y;
    const int b = bh >> 4, h = bh & 15;
    const int tid = threadIdx.x;
    const int ty = tid >> 4, tx = tid & 15;

    const float* Qg = g_q + ((long long)(b * SS + q0)) * DD + h * HDD;
    const float* Kg = g_k + ((long long)b * SS) * DD + h * HDD;
    const float* Vg = g_v + ((long long)b * SS) * DD + h * HDD;

    {
        int r = tid >> 1;
        int c0 = (tid & 1) * 32;
#pragma unroll
        for (int u = 0; u < 8; u++) {
            float4 v = *(const float4*)&Qg[(long long)r * DD + c0 + u * 4];
            Qs[c0 + u*4 + 0][r] = v.x;
            Qs[c0 + u*4 + 1][r] = v.y;
            Qs[c0 + u*4 + 2][r] = v.z;
            Qs[c0 + u*4 + 3][r] = v.w;
        }
    }

    float O[8][4];
#pragma unroll
    for (int i = 0; i < 8; i++)
#pragma unroll
        for (int j = 0; j < 4; j++) O[i][j] = 0.f;
    float m[8], l[8];
#pragma unroll
    for (int i = 0; i < 8; i++) { m[i] = -1e30f; l[i] = 0.f; }

    for (int k0 = 0; k0 < q0 + 128; k0 += 64) {
        __syncthreads();
        {
            int r = tid >> 2;
            int c0 = (tid & 3) * 16;
#pragma unroll
            for (int u = 0; u < 4; u++) {
                float4 kv = *(const float4*)&Kg[(long long)(k0 + r) * DD + c0 + u * 4];
                Ks[c0 + u*4 + 0][r] = kv.x;
                Ks[c0 + u*4 + 1][r] = kv.y;
                Ks[c0 + u*4 + 2][r] = kv.z;
                Ks[c0 + u*4 + 3][r] = kv.w;
                *(float4*)&Vs[r][c0 + u*4] =
                    *(const float4*)&Vg[(long long)(k0 + r) * DD + c0 + u * 4];
            }
        }
        __syncthreads();

        float s[8][4];
#pragma unroll
        for (int i = 0; i < 8; i++)
#pragma unroll
            for (int j = 0; j < 4; j++) s[i][j] = 0.f;
#pragma unroll 8
        for (int d = 0; d < 64; d++) {
            float a[8], bb[4];
            *(float4*)&a[0] = *(const float4*)&Qs[d][ty * 8];
            *(float4*)&a[4] = *(const float4*)&Qs[d][ty * 8 + 4];
            *(float4*)&bb[0] = *(const float4*)&Ks[d][tx * 4];
#pragma unroll
            for (int i = 0; i < 8; i++)
#pragma unroll
                for (int j = 0; j < 4; j++)
                    s[i][j] += a[i] * bb[j];
        }

        if (k0 + 63 > q0) {
#pragma unroll
            for (int i = 0; i < 8; i++)
#pragma unroll
                for (int j = 0; j < 4; j++)
                    s[i][j] = (k0 + tx*4 + j <= q0 + ty*8 + i) ? s[i][j] * 0.125f : -1e30f;
        } else {
#pragma unroll
            for (int i = 0; i < 8; i++)
#pragma unroll
                for (int j = 0; j < 4; j++) s[i][j] *= 0.125f;
        }

#pragma unroll
        for (int i = 0; i < 8; i++) {
            float mx = fmaxf(fmaxf(s[i][0], s[i][1]), fmaxf(s[i][2], s[i][3]));
#pragma unroll
            for (int off = 1; off < 16; off <<= 1)
                mx = fmaxf(mx, __shfl_xor_sync(0xffffffffu, mx, off));
            float mn = fmaxf(m[i], mx);
            float corr = __expf(m[i] - mn);
            float p0 = __expf(s[i][0] - mn);
            float p1 = __expf(s[i][1] - mn);
            float p2 = __expf(s[i][2] - mn);
            float p3 = __expf(s[i][3] - mn);
            *(float4*)&Ps[ty*8 + i][tx*4] = make_float4(p0, p1, p2, p3);
            float sum = p0 + p1 + p2 + p3;
#pragma unroll
            for (int off = 1; off < 16; off <<= 1)
                sum += __shfl_xor_sync(0xffffffffu, sum, off);
            l[i] = l[i] * corr + sum;
            m[i] = mn;
            O[i][0] *= corr; O[i][1] *= corr; O[i][2] *= corr; O[i][3] *= corr;
        }
        __syncthreads();

#pragma unroll 8
        for (int c = 0; c < 64; c++) {
            float bb[4];
            *(float4*)&bb[0] = *(const float4*)&Vs[c][tx * 4];
#pragma unroll
            for (int i = 0; i < 8; i++) {
                float a = Ps[ty*8 + i][c];
                O[i][0] += a*bb[0]; O[i][1] += a*bb[1];
                O[i][2] += a*bb[2]; O[i][3] += a*bb[3];
            }
        }
    }

    float* Og = g_ao + ((long long)(b * SS + q0)) * DD + h * HDD;
#pragma unroll
    for (int i = 0; i < 8; i++) {
        float inv = 1.f / l[i];
        float4 o = make_float4(O[i][0]*inv, O[i][1]*inv, O[i][2]*inv, O[i][3]*inv);
        *(float4*)&Og[(long long)(ty*8 + i) * DD + tx * 4] = o;
    }
}

// ---------------- SwiGLU ----------------
__global__ void swiglu_kernel(const float* __restrict__ in,
                              float* __restrict__ out, int rows) {
    long long i = (long long)blockIdx.x * blockDim.x + threadIdx.x;
    if (i >= (long long)rows * FF) return;
    long long r = i / FF;
    int f = (int)(i - r * FF);
    float a = in[r * 2 * FF + f];
    float bv = in[r * 2 * FF + FF + f];
    out[i] = a * (bv / (1.f + __expf(-bv)));
}

// ---------------- gating ----------------
__global__ void gate_kernel(const float* __restrict__ Wg,
                            const float* __restrict__ bias) {
    int t = blockIdx.x;
    int w = threadIdx.x >> 5, lane = threadIdx.x & 31;
    if (w >= NR) return;
    float s = 0.f;
    const float* xr = g_xn2 + (long long)t * DD;
    for (int i = lane; i < DD; i += 32) s += xr[i] * Wg[i * NR + w];
#pragma unroll
    for (int off = 16; off > 0; off >>= 1)
        s += __shfl_down_sync(0xffffffff, s, off);
    if (lane == 0)
        g_aff[t * NR + w] = 1.f / (1.f + __expf(-(s + bias[w])));
}

// ---------------- per-token top-2 ----------------
__global__ void top2_kernel() {
    int t = blockIdx.x * blockDim.x + threadIdx.x;
    if (t >= TT) return;
    float a[NR];
#pragma unroll
    for (int e = 0; e < NR; e++) a[e] = g_aff[t * NR + e];
    int e1 = 0; float b1 = a[0];
#pragma unroll
    for (int e = 1; e < NR; e++) if (a[e] > b1) { b1 = a[e]; e1 = e; }
    int e2 = -1; float b2 = -1.f;
#pragma unroll
    for (int e = 0; e < NR; e++) if (e != e1 && a[e] > b2) { b2 = a[e]; e2 = e; }
    g_top[t] = make_int2(e1, e2);
}

// ---------------- per-expert capacity selection ----------------
__global__ void select_kernel() {
    __shared__ unsigned long long keys[TT];
    int e = blockIdx.x;
    int tid = threadIdx.x;
    for (int i = tid; i < TT; i += 1024) {
        int2 tp = g_top[i];
        unsigned hi;
        if (tp.x == e || tp.y == e) {
            unsigned ev = __float_as_uint(g_aff[i * NR + e]);
            hi = ~ev;
        } else {
            hi = 0xFFFFFFFFu;
        }
        keys[i] = ((unsigned long long)hi << 32) | (unsigned)i;
    }
    __syncthreads();
    for (int ksz = 2; ksz <= TT; ksz <<= 1) {
        for (int j = ksz >> 1; j > 0; j >>= 1) {
            for (int base = tid; base < TT / 2; base += 1024) {
                int i = ((base & ~(j - 1)) << 1) | (base & (j - 1));
                int p = i + j;
                bool up = ((i & ksz) == 0);
                unsigned long long a = keys[i], b2 = keys[p];
                if ((a > b2) == up) { keys[i] = b2; keys[p] = a; }
            }
            __syncthreads();
        }
    }
    for (int c = tid; c < CAP; c += 1024) {
        unsigned long long kk = keys[c];
        int idx = (int)(kk & 0xFFFFFFFFu);
        bool valid = (unsigned)(kk >> 32) != 0xFFFFFFFFu;
        g_selidx[e * CAP + c] = idx;
        g_selw[e * CAP + c] = valid ? g_aff[idx * NR + e] : 0.f;
    }
}

// ---------------- gather ----------------
__global__ void gather_kernel() {
    int row = blockIdx.x;
    int t = g_selidx[row];
    int i = threadIdx.x * 4;
    float4 v = *(const float4*)&g_xn2[(long long)t * DD + i];
    *(float4*)&g_gath[(long long)row * DD + i] = v;
}

// ---------------- scatter-add ----------------
__global__ void scatter_kernel(float* __restrict__ out) {
    int row = blockIdx.x;
    float w = g_selw[row];
    if (w == 0.f) return;
    int t = g_selidx[row];
    int i = threadIdx.x * 4;
    const float* src = &g_eout[(long long)row * DD + i];
    float* dst = &out[(long long)t * DD + i];
#pragma unroll
    for (int j = 0; j < 4; j++) atomicAdd(dst + j, src[j] * w);
}

// ---------------- host helpers ----------------
static float* sym(const void* s) {
    void* p = nullptr;
    cudaGetSymbolAddress(&p, (const void*)s);
    return (float*)p;
}

static void run_gemm128(const float* A, const float* B, float* C, const float* Add,
                        int M, int N, int K, int lda, int batch,
                        long long sA, long long sB, long long sC) {
    dim3 grid((N + 127) / 128, (M + 127) / 128, batch);
    sgemm128_kernel<<<grid, 256>>>(A, B, C, Add, M, N, K, lda, sA, sB, sC);
}

static void run_tf32(const float* A, const float* B, float* C, const float* Add,
                     int M, int N, int K, int batch,
                     long long sA, long long sB, long long sC) {
    dim3 grid(N / 128, (M + 127) / 128, batch);
    tf32gemm_kernel<<<grid, 256>>>(A, B, C, Add, M, N, K, sA, sB, sC);
}

#define ATT_SMEM (98304)

extern "C" void kernel_launch(void* const* d_in, const int* in_sizes, int n_in,
                              void* d_out, int out_size) {
    const float* x       = (const float*)d_in[0];
    const float* Wq_lat  = (const float*)d_in[2];
    const float* Wkv_lat = (const float*)d_in[3];
    const float* Wrot_q  = (const float*)d_in[4];
    const float* Wrot_k  = (const float*)d_in[5];
    const float* Wq_up   = (const float*)d_in[6];
    const float* Wk_up   = (const float*)d_in[7];
    const float* Wv_up   = (const float*)d_in[8];
    const float* Wout    = (const float*)d_in[9];
    const float* n1w     = (const float*)d_in[10];
    const float* n2w     = (const float*)d_in[11];
    const float* Ws1     = (const float*)d_in[12];
    const float* Ws2     = (const float*)d_in[13];
    const float* Wr1     = (const float*)d_in[14];
    const float* Wr2     = (const float*)d_in[15];
    const float* Wgate   = (const float*)d_in[16];
    const float* ebias   = (const float*)d_in[17];
    float* out = (float*)d_out;

    float* p_xn  = sym(&g_xn);
    float* p_wc  = sym(&g_wcat);
    float* p_z   = sym(&g_z);
    float* p_wqr = sym(&g_wqr);
    float* p_wkr = sym(&g_wkr);
    float* p_qrf = sym(&g_qrf);
    float* p_krf = sym(&g_krf);
    float* p_q   = sym(&g_q);
    float* p_k   = sym(&g_k);
    float* p_v   = sym(&g_v);
    float* p_ao  = sym(&g_ao);
    float* p_x1  = sym(&g_x1);
    float* p_xn2 = sym(&g_xn2);
    float* p_h1  = sym(&g_h1);
    float* p_hs  = sym(&g_hs);
    float* p_ga  = sym(&g_gath);
    float* p_hr  = sym(&g_hr);
    float* p_hr2 = sym(&g_hr2);
    float* p_eo  = sym(&g_eout);

    cudaFuncSetAttribute(fattn_kernel, cudaFuncAttributeMaxDynamicSharedMemorySize, ATT_SMEM);

    // ---- sublayer 1 ----
    rmsnorm_kernel<<<TT, 256>>>(x, n1w, p_xn);
    packcat_kernel<<<(DD * 768 + 255) / 256, 256>>>(Wq_lat, Wkv_lat);
    packrot_kernel<<<(LQ * 512 + 255) / 256, 256>>>(Wrot_q, Wrot_k);
    run_gemm128(p_xn, p_wc, p_z, nullptr, TT, 768, DD, DD, 1, 0, 0, 0);
    run_gemm128(p_z,       p_wqr, p_qrf, nullptr, TT, 512, LQ,  768, 1, 0, 0, 0);
    run_gemm128(p_z + 512, p_wkr, p_krf, nullptr, TT, 512, LKV, 768, 1, 0, 0, 0);
    run_gemm128(p_z,       Wq_up, p_q,   nullptr, TT, DD, LQ,  768, 1, 0, 0, 0);
    run_gemm128(p_z + 512, Wk_up, p_k,   nullptr, TT, DD, LKV, 768, 1, 0, 0, 0);
    run_gemm128(p_z + 512, Wv_up, p_v,   nullptr, TT, DD, LKV, 768, 1, 0, 0, 0);
    rope_kernel<<<(TT * HH * ROT + 255) / 256, 256>>>();
    fattn_kernel<<<dim3(SS / 128, TB * HH), 256, ATT_SMEM>>>();
    run_gemm128(p_ao, Wout, p_x1, x, TT, DD, DD, DD, 1, 0, 0, 0);

    // ---- sublayer 2 ----
    rmsnorm_kernel<<<TT, 256>>>(p_x1, n2w, p_xn2);
    run_tf32(p_xn2, Ws1, p_h1, nullptr, TT, 2 * FF, DD, 1, 0, 0, 0);
    swiglu_kernel<<<(TT * FF + 255) / 256, 256>>>(p_h1, p_hs, TT);
    run_tf32(p_hs, Ws2, out, p_x1, TT, DD, FF, 1, 0, 0, 0);
    gate_kernel<<<TT, 256>>>(Wgate, ebias);
    top2_kernel<<<(TT + 255) / 256, 256>>>();
    select_kernel<<<NR, 1024>>>();
    gather_kernel<<<NR * CAP, 256>>>();
    run_tf32(p_ga, Wr1, p_hr, nullptr, CAP, 2 * FF, DD, NR,
             (long long)CAP * DD, (long long)DD * 2 * FF, (long long)CAP * 2 * FF);
    swiglu_kernel<<<(NR * CAP * FF + 255) / 256, 256>>>(p_hr, p_hr2, NR * CAP);
    run_tf32(p_hr2, Wr2, p_eo, nullptr, CAP, DD, FF, NR,
             (long long)CAP * FF, (long long)FF * DD, (long long)CAP * FF);
    scatter_kernel<<<NR * CAP, 256>>>(out);
}

// round 5
// speedup vs baseline: 3.8629x; 1.0856x over previous
#include <cuda_runtime.h>
#include <cuda_bf16.h>
#include <math.h>

// ---------------- static config ----------------
#define TB 2
#define SS 2048
#define DD 1024
#define HH 16
#define HDD 64
#define ROT 32
#define LQ 512
#define LKV 256
#define FF 1024
#define NR 7
#define CAP 585
#define TT (TB*SS)   // 4096 tokens

#define QC 1536      // q-side concat width: Wq_up(1024) | rot(512)
#define KVC 2560     // kv-side concat width: Wk_up(1024) | Wv_up(1024) | rot(512)

// ---------------- device scratch ----------------
__device__ float g_xn [TT*DD];
__device__ float g_wcat[DD*768];    // Wq_lat || Wkv_lat
__device__ float g_z  [TT*768];     // zq | zkv
__device__ float g_wqc [LQ*QC];     // Wq_up || packed rot q
__device__ float g_wkvc[LKV*KVC];   // Wk_up || Wv_up || packed rot k
__device__ float g_qc [TT*QC];      // q (0..1023, rope overwrites rot half) | qrf (1024..1535)
__device__ float g_kvc[TT*KVC];     // k | v | krf
__device__ float g_ao [TT*DD];
__device__ float g_x1 [TT*DD];
__device__ float g_xn2[TT*DD];
__device__ float g_h1 [TT*2*FF];
__device__ float g_hs [TT*FF];
__device__ float g_aff[TT*NR];
__device__ int2  g_top[TT];
__device__ int   g_selidx[NR*CAP];
__device__ float g_selw  [NR*CAP];
__device__ float g_gath[NR*CAP*DD];
__device__ float g_hr  [NR*CAP*2*FF];
__device__ float g_hr2 [NR*CAP*FF];
__device__ float g_eout[NR*CAP*DD];

// ---------------- helpers ----------------
__device__ __forceinline__ unsigned f2tf32(float f) {
    unsigned u;
    asm("cvt.rna.tf32.f32 %0, %1;" : "=r"(u) : "f"(f));
    return u;
}

__device__ __forceinline__ void mma_tf32(float* c, const unsigned* a, const unsigned* b) {
    asm volatile(
        "mma.sync.aligned.m16n8k8.row.col.f32.tf32.tf32.f32 "
        "{%0,%1,%2,%3}, {%4,%5,%6,%7}, {%8,%9}, {%0,%1,%2,%3};"
        : "+f"(c[0]), "+f"(c[1]), "+f"(c[2]), "+f"(c[3])
        : "r"(a[0]), "r"(a[1]), "r"(a[2]), "r"(a[3]), "r"(b[0]), "r"(b[1]));
}

// ---------------- RMSNorm ----------------
__global__ void rmsnorm_kernel(const float* __restrict__ x,
                               const float* __restrict__ w,
                               float* __restrict__ o) {
    int t = blockIdx.x;
    int tid = threadIdx.x;
    __shared__ float red[256];
    const float4* xr = (const float4*)(x + (long long)t * DD);
    float4 v = xr[tid];
    float ss = v.x*v.x + v.y*v.y + v.z*v.z + v.w*v.w;
    red[tid] = ss; __syncthreads();
    for (int off = 128; off > 0; off >>= 1) {
        if (tid < off) red[tid] += red[tid + off];
        __syncthreads();
    }
    float inv = rsqrtf(red[0] / (float)DD + 1e-6f);
    const float4* wr = (const float4*)w;
    float4 wv = wr[tid];
    float4 ov = make_float4(v.x*inv*wv.x, v.y*inv*wv.y, v.z*inv*wv.z, v.w*inv*wv.w);
    ((float4*)(o + (long long)t * DD))[tid] = ov;
}

// ---------------- SGEMM 128x128x16, 8x8 micro-tile, double-buffered (fp32) ----------------
__global__ void __launch_bounds__(256)
sgemm128_kernel(const float* __restrict__ A,
                const float* __restrict__ B,
                float* __restrict__ C,
                const float* __restrict__ Add,
                int M, int N, int K, int lda) {
    int m0 = blockIdx.y * 128, n0 = blockIdx.x * 128;
    int tid = threadIdx.x;
    int ty = tid >> 4, tx = tid & 15;

    __shared__ __align__(16) float As[2][16][128];
    __shared__ __align__(16) float Bs[2][16][128];

    float acc[8][8];
#pragma unroll
    for (int i = 0; i < 8; i++)
#pragma unroll
        for (int j = 0; j < 8; j++) acc[i][j] = 0.f;

    int arow = tid >> 1;
    int acol = (tid & 1) * 8;
    int brow = tid >> 4;
    int bcol = (tid & 15) * 8;
    bool arowok = (m0 + arow) < M;
    const float* Ap = A + (long long)(m0 + arow) * lda + acol;
    const float* Bp = B + (long long)brow * N + n0 + bcol;

    float4 av0 = make_float4(0,0,0,0), av1 = av0, bv0, bv1;
    if (arowok) {
        av0 = *(const float4*)&Ap[0];
        av1 = *(const float4*)&Ap[4];
    }
    bv0 = *(const float4*)&Bp[0];
    bv1 = *(const float4*)&Bp[4];

    {
        As[0][acol + 0][arow] = av0.x; As[0][acol + 1][arow] = av0.y;
        As[0][acol + 2][arow] = av0.z; As[0][acol + 3][arow] = av0.w;
        As[0][acol + 4][arow] = av1.x; As[0][acol + 5][arow] = av1.y;
        As[0][acol + 6][arow] = av1.z; As[0][acol + 7][arow] = av1.w;
        *(float4*)&Bs[0][brow][bcol] = bv0;
        *(float4*)&Bs[0][brow][bcol + 4] = bv1;
    }
    __syncthreads();

    int nk = K >> 4;
    for (int t = 0; t < nk; t++) {
        int cur = t & 1;
        if (t + 1 < nk) {
            const float* Apn = Ap + (t + 1) * 16;
            const float* Bpn = Bp + (long long)(t + 1) * 16 * N;
            if (arowok) {
                av0 = *(const float4*)&Apn[0];
                av1 = *(const float4*)&Apn[4];
            }
            bv0 = *(const float4*)&Bpn[0];
            bv1 = *(const float4*)&Bpn[4];
        }
#pragma unroll
        for (int kk = 0; kk < 16; kk++) {
            float a[8], b[8];
            *(float4*)&a[0] = *(const float4*)&As[cur][kk][ty * 4];
            *(float4*)&a[4] = *(const float4*)&As[cur][kk][64 + ty * 4];
            *(float4*)&b[0] = *(const float4*)&Bs[cur][kk][tx * 4];
            *(float4*)&b[4] = *(const float4*)&Bs[cur][kk][64 + tx * 4];
#pragma unroll
            for (int i = 0; i < 8; i++)
#pragma unroll
                for (int j = 0; j < 8; j++)
                    acc[i][j] += a[i] * b[j];
        }
        if (t + 1 < nk) {
            int nxt = cur ^ 1;
            As[nxt][acol + 0][arow] = av0.x; As[nxt][acol + 1][arow] = av0.y;
            As[nxt][acol + 2][arow] = av0.z; As[nxt][acol + 3][arow] = av0.w;
            As[nxt][acol + 4][arow] = av1.x; As[nxt][acol + 5][arow] = av1.y;
            As[nxt][acol + 6][arow] = av1.z; As[nxt][acol + 7][arow] = av1.w;
            *(float4*)&Bs[nxt][brow][bcol] = bv0;
            *(float4*)&Bs[nxt][brow][bcol + 4] = bv1;
        }
        __syncthreads();
    }

#pragma unroll
    for (int hi = 0; hi < 2; hi++) {
#pragma unroll
        for (int ii = 0; ii < 4; ii++) {
            int row = m0 + hi * 64 + ty * 4 + ii;
            if (row >= M) continue;
#pragma unroll
            for (int hj = 0; hj < 2; hj++) {
                long long off = (long long)row * N + n0 + hj * 64 + tx * 4;
                int ai = hi * 4 + ii;
                float4 r = make_float4(acc[ai][hj*4+0], acc[ai][hj*4+1],
                                       acc[ai][hj*4+2], acc[ai][hj*4+3]);
                if (Add) {
                    float4 ad = *(const float4*)&Add[off];
                    r.x += ad.x; r.y += ad.y; r.z += ad.z; r.w += ad.w;
                }
                *(float4*)&C[off] = r;
            }
        }
    }
}

// ---------------- TF32 tensor-core GEMM 128x128x16 ----------------
__global__ void __launch_bounds__(256)
tf32gemm_kernel(const float* __restrict__ A,
                const float* __restrict__ B,
                float* __restrict__ C,
                const float* __restrict__ Add,
                int M, int N, int K,
                long long sA, long long sB, long long sC) {
    int z = blockIdx.z;
    A += (long long)z * sA;
    B += (long long)z * sB;
    C += (long long)z * sC;
    if (Add) Add += (long long)z * sC;

    const int m0 = blockIdx.y * 128, n0 = blockIdx.x * 128;
    const int tid = threadIdx.x;
    const int w = tid >> 5, lane = tid & 31;
    const int wm = (w >> 2) * 64;
    const int wn = (w & 3) * 32;
    const int gr = lane >> 2, c4 = lane & 3;

    __shared__ float As[2][16][136];
    __shared__ float Bs[2][16][136];

    float acc[4][4][4];
#pragma unroll
    for (int i = 0; i < 4; i++)
#pragma unroll
        for (int j = 0; j < 4; j++)
#pragma unroll
            for (int r = 0; r < 4; r++) acc[i][j][r] = 0.f;

    const int arow = tid >> 1;
    const int acol = (tid & 1) * 8;
    const int brow = tid >> 4;
    const int bcol = (tid & 15) * 8;
    const bool arowok = (m0 + arow) < M;
    const float* Ap = A + (long long)(m0 + arow) * K + acol;
    const float* Bp = B + (long long)brow * N + n0 + bcol;

    float ar[8], br[8];
#pragma unroll
    for (int j = 0; j < 8; j++) { ar[j] = 0.f; }
    if (arowok) {
        float4 a0 = *(const float4*)&Ap[0];
        float4 a1 = *(const float4*)&Ap[4];
        ar[0]=a0.x; ar[1]=a0.y; ar[2]=a0.z; ar[3]=a0.w;
        ar[4]=a1.x; ar[5]=a1.y; ar[6]=a1.z; ar[7]=a1.w;
    }
    {
        float4 b0 = *(const float4*)&Bp[0];
        float4 b1 = *(const float4*)&Bp[4];
        br[0]=b0.x; br[1]=b0.y; br[2]=b0.z; br[3]=b0.w;
        br[4]=b1.x; br[5]=b1.y; br[6]=b1.z; br[7]=b1.w;
    }
#pragma unroll
    for (int j = 0; j < 8; j++) {
        As[0][acol + j][arow] = __uint_as_float(f2tf32(ar[j]));
        Bs[0][brow][bcol + j] = __uint_as_float(f2tf32(br[j]));
    }
    __syncthreads();

    const int nk = K >> 4;
    for (int t = 0; t < nk; t++) {
        int cur = t & 1;
        if (t + 1 < nk) {
            const float* Apn = Ap + (t + 1) * 16;
            const float* Bpn = Bp + (long long)(t + 1) * 16 * N;
            if (arowok) {
                float4 a0 = *(const float4*)&Apn[0];
                float4 a1 = *(const float4*)&Apn[4];
                ar[0]=a0.x; ar[1]=a0.y; ar[2]=a0.z; ar[3]=a0.w;
                ar[4]=a1.x; ar[5]=a1.y; ar[6]=a1.z; ar[7]=a1.w;
            }
            float4 b0 = *(const float4*)&Bpn[0];
            float4 b1 = *(const float4*)&Bpn[4];
            br[0]=b0.x; br[1]=b0.y; br[2]=b0.z; br[3]=b0.w;
            br[4]=b1.x; br[5]=b1.y; br[6]=b1.z; br[7]=b1.w;
        }
#pragma unroll
        for (int ks = 0; ks < 16; ks += 8) {
            unsigned af[4][4], bf[4][2];
#pragma unroll
            for (int mf = 0; mf < 4; mf++) {
                int am = wm + mf * 16;
                af[mf][0] = __float_as_uint(As[cur][ks + c4    ][am + gr    ]);
                af[mf][1] = __float_as_uint(As[cur][ks + c4    ][am + gr + 8]);
                af[mf][2] = __float_as_uint(As[cur][ks + c4 + 4][am + gr    ]);
                af[mf][3] = __float_as_uint(As[cur][ks + c4 + 4][am + gr + 8]);
            }
#pragma unroll
            for (int nf = 0; nf < 4; nf++) {
                int bn = wn + nf * 8;
                bf[nf][0] = __float_as_uint(Bs[cur][ks + c4    ][bn + gr]);
                bf[nf][1] = __float_as_uint(Bs[cur][ks + c4 + 4][bn + gr]);
            }
#pragma unroll
            for (int mf = 0; mf < 4; mf++)
#pragma unroll
                for (int nf = 0; nf < 4; nf++)
                    mma_tf32(acc[mf][nf], af[mf], bf[nf]);
        }
        if (t + 1 < nk) {
            int nxt = cur ^ 1;
#pragma unroll
            for (int j = 0; j < 8; j++) {
                As[nxt][acol + j][arow] = __uint_as_float(f2tf32(ar[j]));
                Bs[nxt][brow][bcol + j] = __uint_as_float(f2tf32(br[j]));
            }
        }
        __syncthreads();
    }

#pragma unroll
    for (int mf = 0; mf < 4; mf++) {
        int r0 = m0 + wm + mf * 16 + gr;
        int r1 = r0 + 8;
#pragma unroll
        for (int nf = 0; nf < 4; nf++) {
            int col = n0 + wn + nf * 8 + c4 * 2;
            if (r0 < M) {
                float2 v = make_float2(acc[mf][nf][0], acc[mf][nf][1]);
                if (Add) {
                    float2 ad = *(const float2*)&Add[(long long)r0 * N + col];
                    v.x += ad.x; v.y += ad.y;
                }
                *(float2*)&C[(long long)r0 * N + col] = v;
            }
            if (r1 < M) {
                float2 v = make_float2(acc[mf][nf][2], acc[mf][nf][3]);
                if (Add) {
                    float2 ad = *(const float2*)&Add[(long long)r1 * N + col];
                    v.x += ad.x; v.y += ad.y;
                }
                *(float2*)&C[(long long)r1 * N + col] = v;
            }
        }
    }
}

// ---------------- weight pack kernels ----------------
__global__ void packcat_kernel(const float* __restrict__ Wq,
                               const float* __restrict__ Wkv) {
    int idx = blockIdx.x * 256 + threadIdx.x;
    if (idx >= DD * 768) return;
    int r = idx / 768, c = idx % 768;
    g_wcat[idx] = (c < 512) ? Wq[r * 512 + c] : Wkv[r * 256 + (c - 512)];
}

__global__ void packq_kernel(const float* __restrict__ Wq_up,
                             const float* __restrict__ Wrot_q) {
    int idx = blockIdx.x * 256 + threadIdx.x;
    if (idx >= LQ * QC) return;
    int r = idx / QC, c = idx % QC;
    if (c < 1024) {
        g_wqc[idx] = Wq_up[r * 1024 + c];
    } else {
        int cc = c - 1024, h = cc >> 5, j = cc & 31;
        g_wqc[idx] = Wrot_q[r * 1024 + h * 64 + j];
    }
}

__global__ void packkv_kernel(const float* __restrict__ Wk_up,
                              const float* __restrict__ Wv_up,
                              const float* __restrict__ Wrot_k) {
    int idx = blockIdx.x * 256 + threadIdx.x;
    if (idx >= LKV * KVC) return;
    int r = idx / KVC, c = idx % KVC;
    if (c < 1024) {
        g_wkvc[idx] = Wk_up[r * 1024 + c];
    } else if (c < 2048) {
        g_wkvc[idx] = Wv_up[r * 1024 + (c - 1024)];
    } else {
        int cc = c - 2048, h = cc >> 5, j = cc & 31;
        g_wkvc[idx] = Wrot_k[r * 1024 + h * 64 + j];
    }
}

// ---------------- RoPE ----------------
__global__ void rope_kernel() {
    int idx = blockIdx.x * blockDim.x + threadIdx.x;
    if (idx >= TT * HH * ROT) return;
    int j = idx & (ROT - 1);
    int h = (idx >> 5) & (HH - 1);
    int t = idx >> 9;
    int s = t & (SS - 1);
    int i = j & 15;
    float invf = __expf(-9.210340371976184f * (float)i / 16.f);
    float ang = (float)s * invf;
    float sn, c;
    sincosf(ang, &sn, &c);
    long long qb = (long long)t * QC + 1024 + h * 32;
    long long kb = (long long)t * KVC + 2048 + h * 32;
    float qr = g_qc[qb + j];
    float kr = g_kvc[kb + j];
    float qo = (j < 16) ? -g_qc[qb + j + 16] : g_qc[qb + j - 16];
    float ko = (j < 16) ? -g_kvc[kb + j + 16] : g_kvc[kb + j - 16];
    g_qc [(long long)t * QC  + h * HDD + 32 + j] = qr * c + qo * sn;
    g_kvc[(long long)t * KVC + h * HDD + 32 + j] = kr * c + ko * sn;
}

// ---------------- flash attention: 128 queries x 64 keys, 8x4 micro ----------------
__global__ void __launch_bounds__(256)
fattn_kernel(const float* __restrict__ Q, int sq,
             const float* __restrict__ K, int sk,
             const float* __restrict__ V, int sv,
             float* __restrict__ Out, int so) {
    extern __shared__ float sm[];
    float (*Qs)[128] = (float(*)[128])sm;
    float (*Ks)[64]  = (float(*)[64])(sm + 64 * 128);
    float (*Vs)[64]  = (float(*)[64])(sm + 64 * 128 + 64 * 64);
    float (*Ps)[64]  = (float(*)[64])(sm + 64 * 128 + 2 * 64 * 64);

    const int q0 = blockIdx.x * 128;
    const int bh = blockIdx.y;
    const int b = bh >> 4, h = bh & 15;
    const int tid = threadIdx.x;
    const int ty = tid >> 4, tx = tid & 15;

    const float* Qg = Q + (long long)(b * SS + q0) * sq + h * HDD;
    const float* Kg = K + (long long)b * SS * sk + h * HDD;
    const float* Vg = V + (long long)b * SS * sv + h * HDD;

    {
        int r = tid >> 1;
        int c0 = (tid & 1) * 32;
#pragma unroll
        for (int u = 0; u < 8; u++) {
            float4 v = *(const float4*)&Qg[(long long)r * sq + c0 + u * 4];
            Qs[c0 + u*4 + 0][r] = v.x;
            Qs[c0 + u*4 + 1][r] = v.y;
            Qs[c0 + u*4 + 2][r] = v.z;
            Qs[c0 + u*4 + 3][r] = v.w;
        }
    }

    float O[8][4];
#pragma unroll
    for (int i = 0; i < 8; i++)
#pragma unroll
        for (int j = 0; j < 4; j++) O[i][j] = 0.f;
    float m[8], l[8];
#pragma unroll
    for (int i = 0; i < 8; i++) { m[i] = -1e30f; l[i] = 0.f; }

    for (int k0 = 0; k0 < q0 + 128; k0 += 64) {
        __syncthreads();
        {
            int r = tid >> 2;
            int c0 = (tid & 3) * 16;
#pragma unroll
            for (int u = 0; u < 4; u++) {
                float4 kv = *(const float4*)&Kg[(long long)(k0 + r) * sk + c0 + u * 4];
                Ks[c0 + u*4 + 0][r] = kv.x;
                Ks[c0 + u*4 + 1][r] = kv.y;
                Ks[c0 + u*4 + 2][r] = kv.z;
                Ks[c0 + u*4 + 3][r] = kv.w;
                *(float4*)&Vs[r][c0 + u*4] =
                    *(const float4*)&Vg[(long long)(k0 + r) * sv + c0 + u * 4];
            }
        }
        __syncthreads();

        float s[8][4];
#pragma unroll
        for (int i = 0; i < 8; i++)
#pragma unroll
            for (int j = 0; j < 4; j++) s[i][j] = 0.f;
#pragma unroll 8
        for (int d = 0; d < 64; d++) {
            float a[8], bb[4];
            *(float4*)&a[0] = *(const float4*)&Qs[d][ty * 8];
            *(float4*)&a[4] = *(const float4*)&Qs[d][ty * 8 + 4];
            *(float4*)&bb[0] = *(const float4*)&Ks[d][tx * 4];
#pragma unroll
            for (int i = 0; i < 8; i++)
#pragma unroll
                for (int j = 0; j < 4; j++)
                    s[i][j] += a[i] * bb[j];
        }

        if (k0 + 63 > q0) {
#pragma unroll
            for (int i = 0; i < 8; i++)
#pragma unroll
                for (int j = 0; j < 4; j++)
                    s[i][j] = (k0 + tx*4 + j <= q0 + ty*8 + i) ? s[i][j] * 0.125f : -1e30f;
        } else {
#pragma unroll
            for (int i = 0; i < 8; i++)
#pragma unroll
                for (int j = 0; j < 4; j++) s[i][j] *= 0.125f;
        }

#pragma unroll
        for (int i = 0; i < 8; i++) {
            float mx = fmaxf(fmaxf(s[i][0], s[i][1]), fmaxf(s[i][2], s[i][3]));
#pragma unroll
            for (int off = 1; off < 16; off <<= 1)
                mx = fmaxf(mx, __shfl_xor_sync(0xffffffffu, mx, off));
            float mn = fmaxf(m[i], mx);
            float corr = __expf(m[i] - mn);
            float p0 = __expf(s[i][0] - mn);
            float p1 = __expf(s[i][1] - mn);
            float p2 = __expf(s[i][2] - mn);
            float p3 = __expf(s[i][3] - mn);
            *(float4*)&Ps[ty*8 + i][tx*4] = make_float4(p0, p1, p2, p3);
            float sum = p0 + p1 + p2 + p3;
#pragma unroll
            for (int off = 1; off < 16; off <<= 1)
                sum += __shfl_xor_sync(0xffffffffu, sum, off);
            l[i] = l[i] * corr + sum;
            m[i] = mn;
            O[i][0] *= corr; O[i][1] *= corr; O[i][2] *= corr; O[i][3] *= corr;
        }
        __syncthreads();

#pragma unroll 8
        for (int c = 0; c < 64; c++) {
            float bb[4];
            *(float4*)&bb[0] = *(const float4*)&Vs[c][tx * 4];
#pragma unroll
            for (int i = 0; i < 8; i++) {
                float a = Ps[ty*8 + i][c];
                O[i][0] += a*bb[0]; O[i][1] += a*bb[1];
                O[i][2] += a*bb[2]; O[i][3] += a*bb[3];
            }
        }
    }

    float* Og = Out + (long long)(b * SS + q0) * so + h * HDD;
#pragma unroll
    for (int i = 0; i < 8; i++) {
        float inv = 1.f / l[i];
        float4 o = make_float4(O[i][0]*inv, O[i][1]*inv, O[i][2]*inv, O[i][3]*inv);
        *(float4*)&Og[(long long)(ty*8 + i) * so + tx * 4] = o;
    }
}

// ---------------- SwiGLU ----------------
__global__ void swiglu_kernel(const float* __restrict__ in,
                              float* __restrict__ out, int rows) {
    long long i = (long long)blockIdx.x * blockDim.x + threadIdx.x;
    if (i >= (long long)rows * FF) return;
    long long r = i / FF;
    int f = (int)(i - r * FF);
    float a = in[r * 2 * FF + f];
    float bv = in[r * 2 * FF + FF + f];
    out[i] = a * (bv / (1.f + __expf(-bv)));
}

// ---------------- gating ----------------
__global__ void gate_kernel(const float* __restrict__ Wg,
                            const float* __restrict__ bias) {
    int t = blockIdx.x;
    int w = threadIdx.x >> 5, lane = threadIdx.x & 31;
    if (w >= NR) return;
    float s = 0.f;
    const float* xr = g_xn2 + (long long)t * DD;
    for (int i = lane; i < DD; i += 32) s += xr[i] * Wg[i * NR + w];
#pragma unroll
    for (int off = 16; off > 0; off >>= 1)
        s += __shfl_down_sync(0xffffffff, s, off);
    if (lane == 0)
        g_aff[t * NR + w] = 1.f / (1.f + __expf(-(s + bias[w])));
}

// ---------------- per-token top-2 ----------------
__global__ void top2_kernel() {
    int t = blockIdx.x * blockDim.x + threadIdx.x;
    if (t >= TT) return;
    float a[NR];
#pragma unroll
    for (int e = 0; e < NR; e++) a[e] = g_aff[t * NR + e];
    int e1 = 0; float b1 = a[0];
#pragma unroll
    for (int e = 1; e < NR; e++) if (a[e] > b1) { b1 = a[e]; e1 = e; }
    int e2 = -1; float b2 = -1.f;
#pragma unroll
    for (int e = 0; e < NR; e++) if (e != e1 && a[e] > b2) { b2 = a[e]; e2 = e; }
    g_top[t] = make_int2(e1, e2);
}

// ---------------- per-expert capacity selection ----------------
__global__ void select_kernel() {
    __shared__ unsigned long long keys[TT];
    int e = blockIdx.x;
    int tid = threadIdx.x;
    for (int i = tid; i < TT; i += 1024) {
        int2 tp = g_top[i];
        unsigned hi;
        if (tp.x == e || tp.y == e) {
            unsigned ev = __float_as_uint(g_aff[i * NR + e]);
            hi = ~ev;
        } else {
            hi = 0xFFFFFFFFu;
        }
        keys[i] = ((unsigned long long)hi << 32) | (unsigned)i;
    }
    __syncthreads();
    for (int ksz = 2; ksz <= TT; ksz <<= 1) {
        for (int j = ksz >> 1; j > 0; j >>= 1) {
            for (int base = tid; base < TT / 2; base += 1024) {
                int i = ((base & ~(j - 1)) << 1) | (base & (j - 1));
                int p = i + j;
                bool up = ((i & ksz) == 0);
                unsigned long long a = keys[i], b2 = keys[p];
                if ((a > b2) == up) { keys[i] = b2; keys[p] = a; }
            }
            __syncthreads();
        }
    }
    for (int c = tid; c < CAP; c += 1024) {
        unsigned long long kk = keys[c];
        int idx = (int)(kk & 0xFFFFFFFFu);
        bool valid = (unsigned)(kk >> 32) != 0xFFFFFFFFu;
        g_selidx[e * CAP + c] = idx;
        g_selw[e * CAP + c] = valid ? g_aff[idx * NR + e] : 0.f;
    }
}

// ---------------- gather ----------------
__global__ void gather_kernel() {
    int row = blockIdx.x;
    int t = g_selidx[row];
    int i = threadIdx.x * 4;
    float4 v = *(const float4*)&g_xn2[(long long)t * DD + i];
    *(float4*)&g_gath[(long long)row * DD + i] = v;
}

// ---------------- scatter-add ----------------
__global__ void scatter_kernel(float* __restrict__ out) {
    int row = blockIdx.x;
    float w = g_selw[row];
    if (w == 0.f) return;
    int t = g_selidx[row];
    int i = threadIdx.x * 4;
    const float* src = &g_eout[(long long)row * DD + i];
    float* dst = &out[(long long)t * DD + i];
#pragma unroll
    for (int j = 0; j < 4; j++) atomicAdd(dst + j, src[j] * w);
}

// ---------------- host helpers ----------------
static float* sym(const void* s) {
    void* p = nullptr;
    cudaGetSymbolAddress(&p, (const void*)s);
    return (float*)p;
}

static void run_gemm128(cudaStream_t st, const float* A, const float* B, float* C,
                        const float* Add, int M, int N, int K, int lda) {
    dim3 grid((N + 127) / 128, (M + 127) / 128);
    sgemm128_kernel<<<grid, 256, 0, st>>>(A, B, C, Add, M, N, K, lda);
}

static void run_tf32(cudaStream_t st, const float* A, const float* B, float* C,
                     const float* Add, int M, int N, int K, int batch,
                     long long sA, long long sB, long long sC) {
    dim3 grid(N / 128, (M + 127) / 128, batch);
    tf32gemm_kernel<<<grid, 256, 0, st>>>(A, B, C, Add, M, N, K, sA, sB, sC);
}

#define ATT_SMEM (98304)

extern "C" void kernel_launch(void* const* d_in, const int* in_sizes, int n_in,
                              void* d_out, int out_size) {
    const float* x       = (const float*)d_in[0];
    const float* Wq_lat  = (const float*)d_in[2];
    const float* Wkv_lat = (const float*)d_in[3];
    const float* Wrot_q  = (const float*)d_in[4];
    const float* Wrot_k  = (const float*)d_in[5];
    const float* Wq_up   = (const float*)d_in[6];
    const float* Wk_up   = (const float*)d_in[7];
    const float* Wv_up   = (const float*)d_in[8];
    const float* Wout    = (const float*)d_in[9];
    const float* n1w     = (const float*)d_in[10];
    const float* n2w     = (const float*)d_in[11];
    const float* Ws1     = (const float*)d_in[12];
    const float* Ws2     = (const float*)d_in[13];
    const float* Wr1     = (const float*)d_in[14];
    const float* Wr2     = (const float*)d_in[15];
    const float* Wgate   = (const float*)d_in[16];
    const float* ebias   = (const float*)d_in[17];
    float* out = (float*)d_out;

    float* p_xn  = sym(&g_xn);
    float* p_wc  = sym(&g_wcat);
    float* p_z   = sym(&g_z);
    float* p_wqc = sym(&g_wqc);
    float* p_wkvc= sym(&g_wkvc);
    float* p_qc  = sym(&g_qc);
    float* p_kvc = sym(&g_kvc);
    float* p_ao  = sym(&g_ao);
    float* p_x1  = sym(&g_x1);
    float* p_xn2 = sym(&g_xn2);
    float* p_h1  = sym(&g_h1);
    float* p_hs  = sym(&g_hs);
    float* p_ga  = sym(&g_gath);
    float* p_hr  = sym(&g_hr);
    float* p_hr2 = sym(&g_hr2);
    float* p_eo  = sym(&g_eout);

    cudaFuncSetAttribute(fattn_kernel, cudaFuncAttributeMaxDynamicSharedMemorySize, ATT_SMEM);

    cudaStream_t s0 = 0, s1;
    cudaStreamCreateWithFlags(&s1, cudaStreamNonBlocking);
    cudaEvent_t eStart, ePack, eZ, eKV, eR, eMoE;
    cudaEventCreateWithFlags(&eStart, cudaEventDisableTiming);
    cudaEventCreateWithFlags(&ePack, cudaEventDisableTiming);
    cudaEventCreateWithFlags(&eZ, cudaEventDisableTiming);
    cudaEventCreateWithFlags(&eKV, cudaEventDisableTiming);
    cudaEventCreateWithFlags(&eR, cudaEventDisableTiming);
    cudaEventCreateWithFlags(&eMoE, cudaEventDisableTiming);

    // fork: packs on s1, rmsnorm on main
    cudaEventRecord(eStart, s0);
    cudaStreamWaitEvent(s1, eStart, 0);

    rmsnorm_kernel<<<TT, 256, 0, s0>>>(x, n1w, p_xn);
    packcat_kernel<<<(DD * 768 + 255) / 256, 256, 0, s1>>>(Wq_lat, Wkv_lat);
    packq_kernel  <<<(LQ * QC + 255) / 256, 256, 0, s1>>>(Wq_up, Wrot_q);
    packkv_kernel <<<(LKV * KVC + 255) / 256, 256, 0, s1>>>(Wk_up, Wv_up, Wrot_k);
    cudaEventRecord(ePack, s1);
    cudaStreamWaitEvent(s0, ePack, 0);

    // z = xn @ wcat  [TT x 768]
    run_gemm128(s0, p_xn, p_wc, p_z, nullptr, TT, 768, DD, DD);
    cudaEventRecord(eZ, s0);
    cudaStreamWaitEvent(s1, eZ, 0);

    // q-side on main, kv-side on s1 (parallel)
    run_gemm128(s0, p_z,       p_wqc,  p_qc,  nullptr, TT, QC,  LQ,  768);
    run_gemm128(s1, p_z + 512, p_wkvc, p_kvc, nullptr, TT, KVC, LKV, 768);
    cudaEventRecord(eKV, s1);
    cudaStreamWaitEvent(s0, eKV, 0);

    rope_kernel<<<(TT * HH * ROT + 255) / 256, 256, 0, s0>>>();
    fattn_kernel<<<dim3(SS / 128, TB * HH), 256, ATT_SMEM, s0>>>(
        p_qc, QC, p_kvc, KVC, p_kvc + 1024, KVC, p_ao, DD);
    run_gemm128(s0, p_ao, Wout, p_x1, x, TT, DD, DD, DD);
    rmsnorm_kernel<<<TT, 256, 0, s0>>>(p_x1, n2w, p_xn2);
    cudaEventRecord(eR, s0);
    cudaStreamWaitEvent(s1, eR, 0);

    // routed chain on s1
    gate_kernel<<<TT, 256, 0, s1>>>(Wgate, ebias);
    top2_kernel<<<(TT + 255) / 256, 256, 0, s1>>>();
    select_kernel<<<NR, 1024, 0, s1>>>();
    gather_kernel<<<NR * CAP, 256, 0, s1>>>();
    run_tf32(s1, p_ga, Wr1, p_hr, nullptr, CAP, 2 * FF, DD, NR,
             (long long)CAP * DD, (long long)DD * 2 * FF, (long long)CAP * 2 * FF);
    swiglu_kernel<<<(NR * CAP * FF + 255) / 256, 256, 0, s1>>>(p_hr, p_hr2, NR * CAP);
    run_tf32(s1, p_hr2, Wr2, p_eo, nullptr, CAP, DD, FF, NR,
             (long long)CAP * FF, (long long)FF * DD, (long long)CAP * FF);
    cudaEventRecord(eMoE, s1);

    // shared chain on main
    run_tf32(s0, p_xn2, Ws1, p_h1, nullptr, TT, 2 * FF, DD, 1, 0, 0, 0);
    swiglu_kernel<<<(TT * FF + 255) / 256, 256, 0, s0>>>(p_h1, p_hs, TT);
    run_tf32(s0, p_hs, Ws2, out, p_x1, TT, DD, FF, 1, 0, 0, 0);

    // join and scatter
    cudaStreamWaitEvent(s0, eMoE, 0);
    scatter_kernel<<<NR * CAP, 256, 0, s0>>>(out);
}